// round 1
// baseline (speedup 1.0000x reference)
#include <cuda_runtime.h>
#include <math.h>

#define BB 2
#define TT 2048
#define CC 1024
#define HH 16
#define DH 64
#define NROWS (BB*TT)          // 4096

// ---------------- scratch (static device, no allocations) ----------------
__device__ float g_xn [NROWS*CC];
__device__ float g_xt [NROWS*CC];
__device__ float g_qkv[NROWS*3*CC];
__device__ float g_y  [NROWS*CC];
__device__ float g_x1 [NROWS*CC];
__device__ float g_h  [NROWS*CC];
__device__ float g_fc [NROWS*4*CC];

// ---------------- block reduce (256 threads, up to 3 scalars) ----------------
__device__ __forceinline__ void block_reduce(float* vals, int n, float* scr) {
    int tid = threadIdx.x, lane = tid & 31, wid = tid >> 5;
    for (int k = 0; k < n; k++) {
        float v = vals[k];
        #pragma unroll
        for (int o = 16; o; o >>= 1) v += __shfl_xor_sync(0xffffffffu, v, o);
        if (lane == 0) scr[k*8 + wid] = v;
    }
    __syncthreads();
    if (tid == 0) {
        for (int k = 0; k < n; k++) {
            float s = 0.f;
            #pragma unroll
            for (int w = 0; w < 8; w++) s += scr[k*8 + w];
            scr[24 + k] = s;
        }
    }
    __syncthreads();
    for (int k = 0; k < n; k++) vals[k] = scr[24 + k];
    __syncthreads();
}

// ---------------- LayerNorm ----------------
__global__ void ln_kernel(const float* __restrict__ x, const float* __restrict__ w,
                          const float* __restrict__ b, float* __restrict__ out) {
    __shared__ float scr[32];
    int row = blockIdx.x;
    const float* xr = x + (size_t)row * CC;
    float* orow = out + (size_t)row * CC;
    int tid = threadIdx.x;
    float v2[2] = {0.f, 0.f};
    for (int i = tid; i < CC; i += 256) { float v = xr[i]; v2[0] += v; v2[1] += v*v; }
    block_reduce(v2, 2, scr);
    float mean = v2[0] * (1.0f/CC);
    float var  = v2[1] * (1.0f/CC) - mean*mean;
    float inv  = rsqrtf(var + 1e-5f);
    for (int i = tid; i < CC; i += 256)
        orow[i] = (xr[i] - mean) * inv * w[i] + b[i];
}

// ---------------- logmap(ref, xn) -> xt ----------------
__global__ void logmap_kernel(const float* __restrict__ xn, float* __restrict__ xt) {
    __shared__ float scr[32];
    __shared__ float ms[CC];
    int row = blockIdx.x;
    int t = row & (TT - 1);
    const float* u = xn + (size_t)row * CC;
    const float* a = (t == 0) ? nullptr : xn + (size_t)(row - 1) * CC;
    int tid = threadIdx.x;

    float v3[3] = {0.f, 0.f, 0.f};     // an2, un2, ip(a,u)
    for (int i = tid; i < CC; i += 256) {
        float ui = u[i];
        float ai = a ? a[i] : 0.f;
        v3[0] += ai*ai; v3[1] += ui*ui; v3[2] += ai*ui;
    }
    block_reduce(v3, 3, scr);
    float an2 = v3[0], un2 = v3[1], ipau = v3[2];

    // m = mobius_addition(-a, u, 1)
    float coefX = 1.f - 2.f*ipau + un2;     // coefficient on (-a)
    float coefU = 1.f - an2;
    float den   = 1.f - 2.f*ipau + an2*un2;
    float rden  = 1.f / den;

    float mn2v[1] = {0.f};
    for (int i = tid; i < CC; i += 256) {
        float ai = a ? a[i] : 0.f;
        float mi = (coefU * u[i] - coefX * ai) * rden;
        ms[i] = mi;
        mn2v[0] += mi*mi;
    }
    block_reduce(mn2v, 1, scr);
    float mn = sqrtf(mn2v[0]);
    float cf = 1.f + an2;                     // 2/(lam*sqrt(c)), lam=2/(1+an2)
    float arg = fminf(sqrtf(mn), 0.999f);     // reference: sqrt(c*mn), mn = NORM
    float scale = cf * atanhf(arg) / mn;
    float* o = xt + (size_t)row * CC;
    for (int i = tid; i < CC; i += 256) o[i] = scale * ms[i];
}

// ---------------- expmap(ref, y) in-place on y ----------------
__global__ void expmap_kernel(const float* __restrict__ xn, float* __restrict__ y) {
    __shared__ float scr[32];
    int row = blockIdx.x;
    int t = row & (TT - 1);
    const float* xr = (t == 0) ? nullptr : xn + (size_t)(row - 1) * CC;
    float* v = y + (size_t)row * CC;
    int tid = threadIdx.x;

    float v3[3] = {0.f, 0.f, 0.f};  // refn2, vn2, <ref,v>
    for (int i = tid; i < CC; i += 256) {
        float vi = v[i];
        float xi = xr ? xr[i] : 0.f;
        v3[0] += xi*xi; v3[1] += vi*vi; v3[2] += xi*vi;
    }
    block_reduce(v3, 3, scr);
    float refn2 = v3[0], vn2 = v3[1], xv = v3[2];

    float lam = 2.f / (1.f + refn2);
    float vn  = sqrtf(vn2);
    float th  = tanhf(sqrtf(lam * vn2 * 0.5f));
    float ss  = th / vn;                  // second_i = ss * v_i
    float secn2 = th * th;
    float ipxs  = ss * xv;
    float coefX = 1.f + 2.f*ipxs + secn2;
    float coefY = (1.f - refn2) * ss;
    float rden  = 1.f / (1.f + 2.f*ipxs + refn2*secn2);
    for (int i = tid; i < CC; i += 256) {
        float xi = xr ? xr[i] : 0.f;
        v[i] = (coefX * xi + coefY * v[i]) * rden;
    }
}

// ---------------- SGEMM 128x128x8, 8x8 thread tile ----------------
// C[M,N] = A[M,K] @ W[K,N] + bias ; ACT=1 -> exact GELU ; res != null -> +res
template<int ACT>
__global__ void __launch_bounds__(256, 2) sgemm_kernel(
    const float* __restrict__ A, const float* __restrict__ W,
    const float* __restrict__ bias, const float* __restrict__ res,
    float* __restrict__ Cout, int Mdim, int Ndim, int Kdim)
{
    __shared__ float As[8][128];
    __shared__ float Bs[8][128];
    int tid = threadIdx.x;
    int bm = blockIdx.y * 128, bn = blockIdx.x * 128;
    int arow = tid >> 1, acol = (tid & 1) * 4;
    int brow = tid >> 5, bcol = (tid & 31) * 4;
    int ty = tid >> 4, tx = tid & 15;

    float acc[8][8];
    #pragma unroll
    for (int i = 0; i < 8; i++)
        #pragma unroll
        for (int j = 0; j < 8; j++) acc[i][j] = 0.f;

    for (int k0 = 0; k0 < Kdim; k0 += 8) {
        float4 av = *(const float4*)(A + (size_t)(bm + arow) * Kdim + k0 + acol);
        As[acol+0][arow] = av.x; As[acol+1][arow] = av.y;
        As[acol+2][arow] = av.z; As[acol+3][arow] = av.w;
        float4 bv = *(const float4*)(W + (size_t)(k0 + brow) * Ndim + bn + bcol);
        *(float4*)&Bs[brow][bcol] = bv;
        __syncthreads();
        #pragma unroll
        for (int k = 0; k < 8; k++) {
            float af[8], bf[8];
            *(float4*)&af[0] = *(const float4*)&As[k][ty*8];
            *(float4*)&af[4] = *(const float4*)&As[k][ty*8 + 4];
            *(float4*)&bf[0] = *(const float4*)&Bs[k][tx*8];
            *(float4*)&bf[4] = *(const float4*)&Bs[k][tx*8 + 4];
            #pragma unroll
            for (int i = 0; i < 8; i++)
                #pragma unroll
                for (int j = 0; j < 8; j++) acc[i][j] += af[i] * bf[j];
        }
        __syncthreads();
    }
    #pragma unroll
    for (int i = 0; i < 8; i++) {
        size_t row = bm + ty*8 + i;
        #pragma unroll
        for (int j = 0; j < 8; j++) {
            int col = bn + tx*8 + j;
            float v = acc[i][j] + bias[col];
            if (ACT == 1) v = v * normcdff(v);
            if (res) v += res[row * Ndim + col];
            Cout[row * Ndim + col] = v;
        }
    }
}

// ---------------- flash attention fp32, 64x64 tiles ----------------
#define ATTN_SMEM (4 * 64 * 65 * 4)
__global__ void attn_kernel(const float* __restrict__ qkv, float* __restrict__ y) {
    extern __shared__ float sm[];
    const int P = 65;
    float* Qs = sm;
    float* Ks = Qs + 64*P;
    float* Vs = Ks + 64*P;
    float* Ps = Vs + 64*P;

    int bh = blockIdx.y;
    int b = bh >> 4, h = bh & 15;
    int q0 = blockIdx.x * 64;
    int tid = threadIdx.x;
    int ty = tid >> 4, tx = tid & 15;

    const size_t stride_t = 3 * CC;
    const size_t qoff = (size_t)(b*TT) * stride_t + h*DH;

    // load Q tile
    for (int idx = tid*4; idx < 64*64; idx += 1024) {
        int r = idx >> 6, d = idx & 63;
        float4 v = *(const float4*)(qkv + qoff + (size_t)(q0 + r) * stride_t + d);
        Qs[r*P+d] = v.x; Qs[r*P+d+1] = v.y; Qs[r*P+d+2] = v.z; Qs[r*P+d+3] = v.w;
    }

    float o[4][4];
    float mrow[4], lrow[4];
    #pragma unroll
    for (int i = 0; i < 4; i++) {
        mrow[i] = -1e30f; lrow[i] = 0.f;
        #pragma unroll
        for (int j = 0; j < 4; j++) o[i][j] = 0.f;
    }

    int ntiles = blockIdx.x + 1;
    for (int kt = 0; kt < ntiles; kt++) {
        int k0 = kt * 64;
        __syncthreads();
        // load K,V tiles
        for (int idx = tid*4; idx < 64*64; idx += 1024) {
            int r = idx >> 6, d = idx & 63;
            size_t base = (size_t)(b*TT + k0 + r) * stride_t + CC + h*DH + d;
            float4 kv = *(const float4*)(qkv + base);
            Ks[r*P+d] = kv.x; Ks[r*P+d+1] = kv.y; Ks[r*P+d+2] = kv.z; Ks[r*P+d+3] = kv.w;
            float4 vv = *(const float4*)(qkv + base + CC);
            Vs[r*P+d] = vv.x; Vs[r*P+d+1] = vv.y; Vs[r*P+d+2] = vv.z; Vs[r*P+d+3] = vv.w;
        }
        __syncthreads();

        // S = Q K^T / 8
        float s[4][4];
        #pragma unroll
        for (int i = 0; i < 4; i++)
            #pragma unroll
            for (int j = 0; j < 4; j++) s[i][j] = 0.f;
        for (int d = 0; d < 64; d++) {
            float qv[4], kv[4];
            #pragma unroll
            for (int i = 0; i < 4; i++) qv[i] = Qs[(ty*4+i)*P + d];
            #pragma unroll
            for (int j = 0; j < 4; j++) kv[j] = Ks[(tx*4+j)*P + d];
            #pragma unroll
            for (int i = 0; i < 4; i++)
                #pragma unroll
                for (int j = 0; j < 4; j++) s[i][j] += qv[i] * kv[j];
        }
        bool need_mask = (k0 + 63 > q0);     // only the diagonal tile
        #pragma unroll
        for (int i = 0; i < 4; i++) {
            int qg = q0 + ty*4 + i;
            #pragma unroll
            for (int j = 0; j < 4; j++) {
                s[i][j] *= 0.125f;
                if (need_mask && (k0 + tx*4 + j) > qg) s[i][j] = -1e30f;
            }
        }
        // online softmax, row stats via 16-lane shfl
        #pragma unroll
        for (int i = 0; i < 4; i++) {
            float tmax = fmaxf(fmaxf(s[i][0], s[i][1]), fmaxf(s[i][2], s[i][3]));
            #pragma unroll
            for (int off = 8; off; off >>= 1)
                tmax = fmaxf(tmax, __shfl_xor_sync(0xffffffffu, tmax, off));
            float mnew = fmaxf(mrow[i], tmax);
            float alpha = expf(mrow[i] - mnew);
            float psum = 0.f;
            #pragma unroll
            for (int j = 0; j < 4; j++) {
                float p = expf(s[i][j] - mnew);
                s[i][j] = p; psum += p;
            }
            #pragma unroll
            for (int off = 8; off; off >>= 1)
                psum += __shfl_xor_sync(0xffffffffu, psum, off);
            lrow[i] = alpha * lrow[i] + psum;
            mrow[i] = mnew;
            #pragma unroll
            for (int j = 0; j < 4; j++) o[i][j] *= alpha;
            #pragma unroll
            for (int j = 0; j < 4; j++) Ps[(ty*4+i)*P + tx*4 + j] = s[i][j];
        }
        __syncthreads();
        // O += P @ V
        for (int kk = 0; kk < 64; kk++) {
            float pv[4], vv[4];
            #pragma unroll
            for (int i = 0; i < 4; i++) pv[i] = Ps[(ty*4+i)*P + kk];
            #pragma unroll
            for (int j = 0; j < 4; j++) vv[j] = Vs[kk*P + tx*4 + j];
            #pragma unroll
            for (int i = 0; i < 4; i++)
                #pragma unroll
                for (int j = 0; j < 4; j++) o[i][j] += pv[i] * vv[j];
        }
    }
    // write out (y layout [B,T,C] with head offset)
    #pragma unroll
    for (int i = 0; i < 4; i++) {
        float rl = 1.f / lrow[i];
        size_t base = (size_t)(b*TT + q0 + ty*4 + i) * CC + h*DH + tx*4;
        #pragma unroll
        for (int j = 0; j < 4; j++) y[base + j] = o[i][j] * rl;
    }
}

// ---------------- launch ----------------
extern "C" void kernel_launch(void* const* d_in, const int* in_sizes, int n_in,
                              void* d_out, int out_size) {
    const float* x       = (const float*)d_in[0];
    const float* ln1_w   = (const float*)d_in[1];
    const float* ln1_b   = (const float*)d_in[2];
    const float* W_attn  = (const float*)d_in[3];
    const float* b_attn  = (const float*)d_in[4];
    const float* W_aproj = (const float*)d_in[5];
    const float* b_aproj = (const float*)d_in[6];
    const float* ln2_w   = (const float*)d_in[7];
    const float* ln2_b   = (const float*)d_in[8];
    const float* W_fc    = (const float*)d_in[9];
    const float* b_fc    = (const float*)d_in[10];
    const float* W_mproj = (const float*)d_in[11];
    const float* b_mproj = (const float*)d_in[12];
    float* out = (float*)d_out;

    float *xn, *xt, *qkv, *y, *x1, *h, *fc;
    cudaGetSymbolAddress((void**)&xn,  g_xn);
    cudaGetSymbolAddress((void**)&xt,  g_xt);
    cudaGetSymbolAddress((void**)&qkv, g_qkv);
    cudaGetSymbolAddress((void**)&y,   g_y);
    cudaGetSymbolAddress((void**)&x1,  g_x1);
    cudaGetSymbolAddress((void**)&h,   g_h);
    cudaGetSymbolAddress((void**)&fc,  g_fc);

    cudaFuncSetAttribute(attn_kernel, cudaFuncAttributeMaxDynamicSharedMemorySize, ATTN_SMEM);

    // 1. LN1
    ln_kernel<<<NROWS, 256>>>(x, ln1_w, ln1_b, xn);
    // 2. logmap
    logmap_kernel<<<NROWS, 256>>>(xn, xt);
    // 3. QKV GEMM: [4096,1024] @ [1024,3072]
    {
        dim3 g(3*CC/128, NROWS/128);
        sgemm_kernel<0><<<g, 256>>>(xt, W_attn, b_attn, nullptr, qkv, NROWS, 3*CC, CC);
    }
    // 4. causal attention
    {
        dim3 g(TT/64, BB*HH);
        attn_kernel<<<g, 256, ATTN_SMEM>>>(qkv, y);
    }
    // 5. expmap (in-place on y)
    expmap_kernel<<<NROWS, 256>>>(xn, y);
    // 6. aproj + residual: x1 = x + y @ W_aproj + b
    {
        dim3 g(CC/128, NROWS/128);
        sgemm_kernel<0><<<g, 256>>>(y, W_aproj, b_aproj, x, x1, NROWS, CC, CC);
    }
    // 7. LN2
    ln_kernel<<<NROWS, 256>>>(x1, ln2_w, ln2_b, h);
    // 8. FC + GELU: [4096,1024] @ [1024,4096]
    {
        dim3 g(4*CC/128, NROWS/128);
        sgemm_kernel<1><<<g, 256>>>(h, W_fc, b_fc, nullptr, fc, NROWS, 4*CC, CC);
    }
    // 9. mproj + residual -> out
    {
        dim3 g(CC/128, NROWS/128);
        sgemm_kernel<0><<<g, 256>>>(fc, W_mproj, b_mproj, x1, out, NROWS, CC, 4*CC);
    }
}

// round 3
// speedup vs baseline: 1.7230x; 1.7230x over previous
#include <cuda_runtime.h>
#include <cuda_bf16.h>
#include <math.h>
#include <stdint.h>

#define BB 2
#define TT 2048
#define CC 1024
#define HH 16
#define DH 64
#define NROWS (BB*TT)          // 4096

// ================= static scratch =================
__device__ float g_xn [NROWS*CC];
__device__ float g_qkv[NROWS*3*CC];
__device__ float g_y  [NROWS*CC];
__device__ float g_x1 [NROWS*CC];

__device__ __nv_bfloat16 g_xt_h[NROWS*CC],   g_xt_l[NROWS*CC];
__device__ __nv_bfloat16 g_y_h [NROWS*CC],   g_y_l [NROWS*CC];
__device__ __nv_bfloat16 g_h_h [NROWS*CC],   g_h_l [NROWS*CC];
__device__ __nv_bfloat16 g_fc_h[NROWS*4*CC], g_fc_l[NROWS*4*CC];

// transposed split weights: [N, K] bf16
__device__ __nv_bfloat16 g_wattn_h [3*CC*CC], g_wattn_l [3*CC*CC];
__device__ __nv_bfloat16 g_waproj_h[CC*CC],   g_waproj_l[CC*CC];
__device__ __nv_bfloat16 g_wfc_h   [4*CC*CC], g_wfc_l   [4*CC*CC];
__device__ __nv_bfloat16 g_wmproj_h[CC*4*CC], g_wmproj_l[CC*4*CC];

// ================= helpers =================
__device__ __forceinline__ uint32_t smem_u32(const void* p) {
    uint32_t a;
    asm("{ .reg .u64 t; cvta.to.shared.u64 t, %1; cvt.u32.u64 %0, t; }" : "=r"(a) : "l"(p));
    return a;
}
#define SWZ(x) ((x) ^ (((x) >> 3) & 0x70))

__device__ __forceinline__ void cp16(uint32_t sa, const void* g) {
    asm volatile("cp.async.cg.shared.global [%0], [%1], 16;" :: "r"(sa), "l"(g));
}
#define CP_COMMIT() asm volatile("cp.async.commit_group;" ::: "memory")
template <int N> __device__ __forceinline__ void cpwait() {
    asm volatile("cp.async.wait_group %0;" :: "n"(N) : "memory");
}

__device__ __forceinline__ void ldsm4(uint32_t& r0, uint32_t& r1, uint32_t& r2, uint32_t& r3, uint32_t a) {
    asm volatile("ldmatrix.sync.aligned.m8n8.x4.shared.b16 {%0,%1,%2,%3}, [%4];"
        : "=r"(r0), "=r"(r1), "=r"(r2), "=r"(r3) : "r"(a));
}
__device__ __forceinline__ void mma16816(float* c, const uint32_t* a, const uint32_t* b) {
    asm volatile("mma.sync.aligned.m16n8k16.row.col.f32.bf16.bf16.f32 "
        "{%0,%1,%2,%3}, {%4,%5,%6,%7}, {%8,%9}, {%0,%1,%2,%3};"
        : "+f"(c[0]), "+f"(c[1]), "+f"(c[2]), "+f"(c[3])
        : "r"(a[0]), "r"(a[1]), "r"(a[2]), "r"(a[3]), "r"(b[0]), "r"(b[1]));
}

__device__ __forceinline__ void split2(float v, __nv_bfloat16& h, __nv_bfloat16& l) {
    h = __float2bfloat16(v);
    l = __float2bfloat16(v - __bfloat162float(h));
}

// ================= block reduce (256 thr) =================
__device__ __forceinline__ void block_reduce(float* vals, int n, float* scr) {
    int tid = threadIdx.x, lane = tid & 31, wid = tid >> 5;
    for (int k = 0; k < n; k++) {
        float v = vals[k];
        #pragma unroll
        for (int o = 16; o; o >>= 1) v += __shfl_xor_sync(0xffffffffu, v, o);
        if (lane == 0) scr[k*8 + wid] = v;
    }
    __syncthreads();
    if (tid == 0) {
        for (int k = 0; k < n; k++) {
            float s = 0.f;
            #pragma unroll
            for (int w = 0; w < 8; w++) s += scr[k*8 + w];
            scr[24 + k] = s;
        }
    }
    __syncthreads();
    for (int k = 0; k < n; k++) vals[k] = scr[24 + k];
    __syncthreads();
}

// ================= LayerNorm (fp32 out) =================
__global__ void ln_kernel(const float* __restrict__ x, const float* __restrict__ w,
                          const float* __restrict__ b, float* __restrict__ out) {
    __shared__ float scr[32];
    int row = blockIdx.x;
    const float* xr = x + (size_t)row * CC;
    float* orow = out + (size_t)row * CC;
    int tid = threadIdx.x;
    float v2[2] = {0.f, 0.f};
    for (int i = tid; i < CC; i += 256) { float v = xr[i]; v2[0] += v; v2[1] += v*v; }
    block_reduce(v2, 2, scr);
    float mean = v2[0] * (1.0f/CC);
    float var  = v2[1] * (1.0f/CC) - mean*mean;
    float inv  = rsqrtf(var + 1e-5f);
    for (int i = tid; i < CC; i += 256)
        orow[i] = (xr[i] - mean) * inv * w[i] + b[i];
}

// ================= LayerNorm (bf16 pair out) =================
__global__ void ln_pair_kernel(const float* __restrict__ x, const float* __restrict__ w,
                               const float* __restrict__ b,
                               __nv_bfloat16* __restrict__ oh, __nv_bfloat16* __restrict__ ol) {
    __shared__ float scr[32];
    int row = blockIdx.x;
    const float* xr = x + (size_t)row * CC;
    int tid = threadIdx.x;
    float v2[2] = {0.f, 0.f};
    for (int i = tid; i < CC; i += 256) { float v = xr[i]; v2[0] += v; v2[1] += v*v; }
    block_reduce(v2, 2, scr);
    float mean = v2[0] * (1.0f/CC);
    float var  = v2[1] * (1.0f/CC) - mean*mean;
    float inv  = rsqrtf(var + 1e-5f);
    size_t base = (size_t)row * CC;
    for (int i = tid; i < CC; i += 256) {
        float v = (xr[i] - mean) * inv * w[i] + b[i];
        __nv_bfloat16 h, l; split2(v, h, l);
        oh[base + i] = h; ol[base + i] = l;
    }
}

// ================= logmap -> bf16 pair =================
__global__ void logmap_kernel(const float* __restrict__ xn,
                              __nv_bfloat16* __restrict__ oh, __nv_bfloat16* __restrict__ ol) {
    __shared__ float scr[32];
    __shared__ float ms[CC];
    int row = blockIdx.x;
    int t = row & (TT - 1);
    const float* u = xn + (size_t)row * CC;
    const float* a = (t == 0) ? nullptr : xn + (size_t)(row - 1) * CC;
    int tid = threadIdx.x;

    float v3[3] = {0.f, 0.f, 0.f};
    for (int i = tid; i < CC; i += 256) {
        float ui = u[i];
        float ai = a ? a[i] : 0.f;
        v3[0] += ai*ai; v3[1] += ui*ui; v3[2] += ai*ui;
    }
    block_reduce(v3, 3, scr);
    float an2 = v3[0], un2 = v3[1], ipau = v3[2];

    float coefX = 1.f - 2.f*ipau + un2;
    float coefU = 1.f - an2;
    float den   = 1.f - 2.f*ipau + an2*un2;
    float rden  = 1.f / den;

    float mn2v[1] = {0.f};
    for (int i = tid; i < CC; i += 256) {
        float ai = a ? a[i] : 0.f;
        float mi = (coefU * u[i] - coefX * ai) * rden;
        ms[i] = mi;
        mn2v[0] += mi*mi;
    }
    block_reduce(mn2v, 1, scr);
    float mn = sqrtf(mn2v[0]);
    float cf = 1.f + an2;
    float arg = fminf(sqrtf(mn), 0.999f);
    float scale = cf * atanhf(arg) / mn;
    size_t base = (size_t)row * CC;
    for (int i = tid; i < CC; i += 256) {
        __nv_bfloat16 h, l; split2(scale * ms[i], h, l);
        oh[base + i] = h; ol[base + i] = l;
    }
}

// ================= expmap: y fp32 -> bf16 pair =================
__global__ void expmap_kernel(const float* __restrict__ xn, const float* __restrict__ y,
                              __nv_bfloat16* __restrict__ oh, __nv_bfloat16* __restrict__ ol) {
    __shared__ float scr[32];
    int row = blockIdx.x;
    int t = row & (TT - 1);
    const float* xr = (t == 0) ? nullptr : xn + (size_t)(row - 1) * CC;
    const float* v = y + (size_t)row * CC;
    int tid = threadIdx.x;

    float v3[3] = {0.f, 0.f, 0.f};
    for (int i = tid; i < CC; i += 256) {
        float vi = v[i];
        float xi = xr ? xr[i] : 0.f;
        v3[0] += xi*xi; v3[1] += vi*vi; v3[2] += xi*vi;
    }
    block_reduce(v3, 3, scr);
    float refn2 = v3[0], vn2 = v3[1], xv = v3[2];

    float lam = 2.f / (1.f + refn2);
    float vn  = sqrtf(vn2);
    float th  = tanhf(sqrtf(lam * vn2 * 0.5f));
    float ss  = th / vn;
    float secn2 = th * th;
    float ipxs  = ss * xv;
    float coefX = 1.f + 2.f*ipxs + secn2;
    float coefY = (1.f - refn2) * ss;
    float rden  = 1.f / (1.f + 2.f*ipxs + refn2*secn2);
    size_t base = (size_t)row * CC;
    for (int i = tid; i < CC; i += 256) {
        float xi = xr ? xr[i] : 0.f;
        float r = (coefX * xi + coefY * v[i]) * rden;
        __nv_bfloat16 h, l; split2(r, h, l);
        oh[base + i] = h; ol[base + i] = l;
    }
}

// ================= weight transpose + split: W[K,N] -> Wt[N,K] bf16 pair =================
__global__ void wsplit_kernel(const float* __restrict__ W,
                              __nv_bfloat16* __restrict__ Wh, __nv_bfloat16* __restrict__ Wl,
                              int K, int N) {
    __shared__ float t[32][33];
    int n0 = blockIdx.x * 32, k0 = blockIdx.y * 32;
    int tx = threadIdx.x, ty = threadIdx.y;   // 32 x 8
    #pragma unroll
    for (int j = 0; j < 32; j += 8)
        t[ty + j][tx] = W[(size_t)(k0 + ty + j) * N + n0 + tx];
    __syncthreads();
    #pragma unroll
    for (int j = 0; j < 32; j += 8) {
        float v = t[tx][ty + j];
        __nv_bfloat16 h, l; split2(v, h, l);
        size_t o = (size_t)(n0 + ty + j) * K + k0 + tx;
        Wh[o] = h; Wl[o] = l;
    }
}

// ================= HMMA bf16x3 GEMM =================
// D[M,N] = (Ah+Al)[M,K] @ (Bh+Bl)^T  (B stored [N,K]) + bias
//   EPI 0: fp32 out      EPI 1: fp32 out + residual     EPI 2: gelu -> bf16 pair
// 256 threads, 8 warps (2 x 4), warptile 64x32, BM=BN=128, BK=64, 2-stage cp.async.
#define TILEB 16384                      // 128 rows x 128B (64 bf16)
#define STAGEB (4*TILEB)                 // Ah, Al, Bh, Bl
#define GSMEM (2*STAGEB)                 // 131072

__device__ __forceinline__ void load_tile(uint32_t sdst, const __nv_bfloat16* g,
                                          int row0, int Kd, int k0, int tid) {
    const __nv_bfloat16* base = g + (size_t)row0 * Kd + k0;
    #pragma unroll
    for (int i = 0; i < 4; i++) {
        int idx = tid * 4 + i;          // 0..1023
        int r = idx >> 3, gc = idx & 7; // row 0..127, 16B group 0..7
        uint32_t so = sdst + SWZ((uint32_t)(r * 128 + gc * 16));
        cp16(so, base + (size_t)r * Kd + gc * 8);
    }
}

template<int EPI>
__global__ void __launch_bounds__(256, 1) gemm_bf16x3(
    const __nv_bfloat16* __restrict__ Ah, const __nv_bfloat16* __restrict__ Al,
    const __nv_bfloat16* __restrict__ Bh, const __nv_bfloat16* __restrict__ Bl,
    const float* __restrict__ bias, const float* __restrict__ res,
    float* __restrict__ Cf, __nv_bfloat16* __restrict__ Coh, __nv_bfloat16* __restrict__ Col,
    int Nd, int Kd)
{
    extern __shared__ __align__(1024) char smem[];
    uint32_t sb = smem_u32(smem);
    int tid = threadIdx.x, wid = tid >> 5, lane = tid & 31;
    int wm = wid >> 2, wn = wid & 3;               // 2 x 4 warp grid
    int bm = blockIdx.y * 128, bn = blockIdx.x * 128;

    float acc[4][4][4];
    #pragma unroll
    for (int mt = 0; mt < 4; mt++)
        #pragma unroll
        for (int nt = 0; nt < 4; nt++)
            #pragma unroll
            for (int r = 0; r < 4; r++) acc[mt][nt][r] = 0.f;

    int nch = Kd >> 6;

    // prologue: stages 0,1
    #pragma unroll
    for (int s = 0; s < 2; s++) {
        uint32_t st = sb + s * STAGEB;
        int k0 = s * 64;
        load_tile(st,           Ah, bm, Kd, k0, tid);
        load_tile(st +   TILEB, Al, bm, Kd, k0, tid);
        load_tile(st + 2*TILEB, Bh, bn, Kd, k0, tid);
        load_tile(st + 3*TILEB, Bl, bn, Kd, k0, tid);
        CP_COMMIT();
    }

    // precomputed ldmatrix lane-address components
    int grp = lane >> 3, rw = lane & 7;
    // A: g0:(m0-7,k0) g1:(m8-15,k0) g2:(m0-7,k8) g3:(m8-15,k8)
    int a_row = (grp & 1) * 8 + rw;            // within 16-row mtile
    int a_kb  = (grp >> 1) * 16;               // byte offset within k16 (bf16*2)
    // B: g0:(n0-7,k0) g1:(n0-7,k8) g2:(n8-15,k0) g3:(n8-15,k8)
    int b_row = (grp >> 1) * 8 + rw;           // within 16-col pair of ntiles
    int b_kb  = (grp & 1) * 16;

    for (int c = 0; c < nch; c++) {
        if (c + 1 < nch) cpwait<1>(); else cpwait<0>();
        __syncthreads();
        uint32_t st = sb + (c & 1) * STAGEB;
        uint32_t Ahs = st, Als = st + TILEB, Bhs = st + 2*TILEB, Bls = st + 3*TILEB;

        #pragma unroll
        for (int kk = 0; kk < 4; kk++) {
            uint32_t ah[4][4], al[4][4], bh[4][2], bl[4][2];
            #pragma unroll
            for (int mt = 0; mt < 4; mt++) {
                uint32_t off = SWZ((uint32_t)((wm*64 + mt*16 + a_row) * 128 + kk*32 + a_kb));
                ldsm4(ah[mt][0], ah[mt][1], ah[mt][2], ah[mt][3], Ahs + off);
                ldsm4(al[mt][0], al[mt][1], al[mt][2], al[mt][3], Als + off);
            }
            #pragma unroll
            for (int p = 0; p < 2; p++) {
                uint32_t off = SWZ((uint32_t)((wn*32 + p*16 + b_row) * 128 + kk*32 + b_kb));
                ldsm4(bh[2*p][0], bh[2*p][1], bh[2*p+1][0], bh[2*p+1][1], Bhs + off);
                ldsm4(bl[2*p][0], bl[2*p][1], bl[2*p+1][0], bl[2*p+1][1], Bls + off);
            }
            #pragma unroll
            for (int mt = 0; mt < 4; mt++)
                #pragma unroll
                for (int nt = 0; nt < 4; nt++) {
                    mma16816(acc[mt][nt], ah[mt], bh[nt]);
                    mma16816(acc[mt][nt], ah[mt], bl[nt]);
                    mma16816(acc[mt][nt], al[mt], bh[nt]);
                }
        }
        __syncthreads();
        int cn = c + 2;
        if (cn < nch) {
            int k0 = cn * 64;
            load_tile(st,           Ah, bm, Kd, k0, tid);
            load_tile(st +   TILEB, Al, bm, Kd, k0, tid);
            load_tile(st + 2*TILEB, Bh, bn, Kd, k0, tid);
            load_tile(st + 3*TILEB, Bl, bn, Kd, k0, tid);
            CP_COMMIT();
        }
    }

    // epilogue
    int r0 = lane >> 2, c0 = (lane & 3) * 2;
    #pragma unroll
    for (int mt = 0; mt < 4; mt++) {
        #pragma unroll
        for (int nt = 0; nt < 4; nt++) {
            int col = bn + wn*32 + nt*8 + c0;
            float b0 = bias[col], b1 = bias[col + 1];
            #pragma unroll
            for (int half = 0; half < 2; half++) {
                int row = bm + wm*64 + mt*16 + r0 + half*8;
                float v0 = acc[mt][nt][half*2]     + b0;
                float v1 = acc[mt][nt][half*2 + 1] + b1;
                size_t off = (size_t)row * Nd + col;
                if (EPI == 2) {
                    v0 = v0 * normcdff(v0);
                    v1 = v1 * normcdff(v1);
                    __nv_bfloat16 h0, l0, h1, l1;
                    split2(v0, h0, l0); split2(v1, h1, l1);
                    *reinterpret_cast<__nv_bfloat162*>(Coh + off) = __nv_bfloat162(h0, h1);
                    *reinterpret_cast<__nv_bfloat162*>(Col + off) = __nv_bfloat162(l0, l1);
                } else {
                    if (EPI == 1) { v0 += res[off]; v1 += res[off + 1]; }
                    *reinterpret_cast<float2*>(Cf + off) = make_float2(v0, v1);
                }
            }
        }
    }
}

// ================= flash attention fp32 =================
#define ATTN_SMEM (4 * 64 * 65 * 4)
__global__ void attn_kernel(const float* __restrict__ qkv, float* __restrict__ y) {
    extern __shared__ float sm[];
    const int P = 65;
    float* Qs = sm;
    float* Ks = Qs + 64*P;
    float* Vs = Ks + 64*P;
    float* Ps = Vs + 64*P;

    int bh = blockIdx.y;
    int b = bh >> 4, h = bh & 15;
    int q0 = blockIdx.x * 64;
    int tid = threadIdx.x;
    int ty = tid >> 4, tx = tid & 15;

    const size_t stride_t = 3 * CC;
    const size_t qoff = (size_t)(b*TT) * stride_t + h*DH;

    for (int idx = tid*4; idx < 64*64; idx += 1024) {
        int r = idx >> 6, d = idx & 63;
        float4 v = *(const float4*)(qkv + qoff + (size_t)(q0 + r) * stride_t + d);
        Qs[r*P+d] = v.x; Qs[r*P+d+1] = v.y; Qs[r*P+d+2] = v.z; Qs[r*P+d+3] = v.w;
    }

    float o[4][4];
    float mrow[4], lrow[4];
    #pragma unroll
    for (int i = 0; i < 4; i++) {
        mrow[i] = -1e30f; lrow[i] = 0.f;
        #pragma unroll
        for (int j = 0; j < 4; j++) o[i][j] = 0.f;
    }

    int ntiles = blockIdx.x + 1;
    for (int kt = 0; kt < ntiles; kt++) {
        int k0 = kt * 64;
        __syncthreads();
        for (int idx = tid*4; idx < 64*64; idx += 1024) {
            int r = idx >> 6, d = idx & 63;
            size_t base = (size_t)(b*TT + k0 + r) * stride_t + CC + h*DH + d;
            float4 kv = *(const float4*)(qkv + base);
            Ks[r*P+d] = kv.x; Ks[r*P+d+1] = kv.y; Ks[r*P+d+2] = kv.z; Ks[r*P+d+3] = kv.w;
            float4 vv = *(const float4*)(qkv + base + CC);
            Vs[r*P+d] = vv.x; Vs[r*P+d+1] = vv.y; Vs[r*P+d+2] = vv.z; Vs[r*P+d+3] = vv.w;
        }
        __syncthreads();

        float s[4][4];
        #pragma unroll
        for (int i = 0; i < 4; i++)
            #pragma unroll
            for (int j = 0; j < 4; j++) s[i][j] = 0.f;
        for (int d = 0; d < 64; d++) {
            float qv[4], kv[4];
            #pragma unroll
            for (int i = 0; i < 4; i++) qv[i] = Qs[(ty*4+i)*P + d];
            #pragma unroll
            for (int j = 0; j < 4; j++) kv[j] = Ks[(tx*4+j)*P + d];
            #pragma unroll
            for (int i = 0; i < 4; i++)
                #pragma unroll
                for (int j = 0; j < 4; j++) s[i][j] += qv[i] * kv[j];
        }
        bool need_mask = (k0 + 63 > q0);
        #pragma unroll
        for (int i = 0; i < 4; i++) {
            int qg = q0 + ty*4 + i;
            #pragma unroll
            for (int j = 0; j < 4; j++) {
                s[i][j] *= 0.125f;
                if (need_mask && (k0 + tx*4 + j) > qg) s[i][j] = -1e30f;
            }
        }
        #pragma unroll
        for (int i = 0; i < 4; i++) {
            float tmax = fmaxf(fmaxf(s[i][0], s[i][1]), fmaxf(s[i][2], s[i][3]));
            #pragma unroll
            for (int off = 8; off; off >>= 1)
                tmax = fmaxf(tmax, __shfl_xor_sync(0xffffffffu, tmax, off));
            float mnew = fmaxf(mrow[i], tmax);
            float alpha = expf(mrow[i] - mnew);
            float psum = 0.f;
            #pragma unroll
            for (int j = 0; j < 4; j++) {
                float pp = expf(s[i][j] - mnew);
                s[i][j] = pp; psum += pp;
            }
            #pragma unroll
            for (int off = 8; off; off >>= 1)
                psum += __shfl_xor_sync(0xffffffffu, psum, off);
            lrow[i] = alpha * lrow[i] + psum;
            mrow[i] = mnew;
            #pragma unroll
            for (int j = 0; j < 4; j++) o[i][j] *= alpha;
            #pragma unroll
            for (int j = 0; j < 4; j++) Ps[(ty*4+i)*P + tx*4 + j] = s[i][j];
        }
        __syncthreads();
        for (int kk = 0; kk < 64; kk++) {
            float pv[4], vv[4];
            #pragma unroll
            for (int i = 0; i < 4; i++) pv[i] = Ps[(ty*4+i)*P + kk];
            #pragma unroll
            for (int j = 0; j < 4; j++) vv[j] = Vs[kk*P + tx*4 + j];
            #pragma unroll
            for (int i = 0; i < 4; i++)
                #pragma unroll
                for (int j = 0; j < 4; j++) o[i][j] += pv[i] * vv[j];
        }
    }
    #pragma unroll
    for (int i = 0; i < 4; i++) {
        float rl = 1.f / lrow[i];
        size_t base = (size_t)(b*TT + q0 + ty*4 + i) * CC + h*DH + tx*4;
        #pragma unroll
        for (int j = 0; j < 4; j++) y[base + j] = o[i][j] * rl;
    }
}

// ================= launch =================
extern "C" void kernel_launch(void* const* d_in, const int* in_sizes, int n_in,
                              void* d_out, int out_size) {
    const float* x       = (const float*)d_in[0];
    const float* ln1_w   = (const float*)d_in[1];
    const float* ln1_b   = (const float*)d_in[2];
    const float* W_attn  = (const float*)d_in[3];
    const float* b_attn  = (const float*)d_in[4];
    const float* W_aproj = (const float*)d_in[5];
    const float* b_aproj = (const float*)d_in[6];
    const float* ln2_w   = (const float*)d_in[7];
    const float* ln2_b   = (const float*)d_in[8];
    const float* W_fc    = (const float*)d_in[9];
    const float* b_fc    = (const float*)d_in[10];
    const float* W_mproj = (const float*)d_in[11];
    const float* b_mproj = (const float*)d_in[12];
    float* out = (float*)d_out;

    float *xn, *qkv, *y, *x1;
    __nv_bfloat16 *xth, *xtl, *yh, *yl, *hh, *hl, *fch, *fcl;
    __nv_bfloat16 *wah, *wal, *wph, *wpl, *wfh, *wfl, *wmh, *wml;
    cudaGetSymbolAddress((void**)&xn,  g_xn);
    cudaGetSymbolAddress((void**)&qkv, g_qkv);
    cudaGetSymbolAddress((void**)&y,   g_y);
    cudaGetSymbolAddress((void**)&x1,  g_x1);
    cudaGetSymbolAddress((void**)&xth, g_xt_h); cudaGetSymbolAddress((void**)&xtl, g_xt_l);
    cudaGetSymbolAddress((void**)&yh,  g_y_h);  cudaGetSymbolAddress((void**)&yl,  g_y_l);
    cudaGetSymbolAddress((void**)&hh,  g_h_h);  cudaGetSymbolAddress((void**)&hl,  g_h_l);
    cudaGetSymbolAddress((void**)&fch, g_fc_h); cudaGetSymbolAddress((void**)&fcl, g_fc_l);
    cudaGetSymbolAddress((void**)&wah, g_wattn_h);  cudaGetSymbolAddress((void**)&wal, g_wattn_l);
    cudaGetSymbolAddress((void**)&wph, g_waproj_h); cudaGetSymbolAddress((void**)&wpl, g_waproj_l);
    cudaGetSymbolAddress((void**)&wfh, g_wfc_h);    cudaGetSymbolAddress((void**)&wfl, g_wfc_l);
    cudaGetSymbolAddress((void**)&wmh, g_wmproj_h); cudaGetSymbolAddress((void**)&wml, g_wmproj_l);

    cudaFuncSetAttribute(attn_kernel, cudaFuncAttributeMaxDynamicSharedMemorySize, ATTN_SMEM);
    cudaFuncSetAttribute(gemm_bf16x3<0>, cudaFuncAttributeMaxDynamicSharedMemorySize, GSMEM);
    cudaFuncSetAttribute(gemm_bf16x3<1>, cudaFuncAttributeMaxDynamicSharedMemorySize, GSMEM);
    cudaFuncSetAttribute(gemm_bf16x3<2>, cudaFuncAttributeMaxDynamicSharedMemorySize, GSMEM);

    dim3 tb(32, 8);
    wsplit_kernel<<<dim3(3*CC/32, CC/32), tb>>>(W_attn,  wah, wal, CC,   3*CC);
    wsplit_kernel<<<dim3(CC/32,   CC/32), tb>>>(W_aproj, wph, wpl, CC,   CC);
    wsplit_kernel<<<dim3(4*CC/32, CC/32), tb>>>(W_fc,    wfh, wfl, CC,   4*CC);
    wsplit_kernel<<<dim3(CC/32, 4*CC/32), tb>>>(W_mproj, wmh, wml, 4*CC, CC);

    // 1. LN1
    ln_kernel<<<NROWS, 256>>>(x, ln1_w, ln1_b, xn);
    // 2. logmap -> xt pair
    logmap_kernel<<<NROWS, 256>>>(xn, xth, xtl);
    // 3. QKV GEMM
    gemm_bf16x3<0><<<dim3(3*CC/128, NROWS/128), 256, GSMEM>>>(
        xth, xtl, wah, wal, b_attn, nullptr, qkv, nullptr, nullptr, 3*CC, CC);
    // 4. attention
    {
        dim3 g(TT/64, BB*HH);
        attn_kernel<<<g, 256, ATTN_SMEM>>>(qkv, y);
    }
    // 5. expmap -> y pair
    expmap_kernel<<<NROWS, 256>>>(xn, y, yh, yl);
    // 6. aproj + residual -> x1 fp32
    gemm_bf16x3<1><<<dim3(CC/128, NROWS/128), 256, GSMEM>>>(
        yh, yl, wph, wpl, b_aproj, x, x1, nullptr, nullptr, CC, CC);
    // 7. LN2 -> h pair
    ln_pair_kernel<<<NROWS, 256>>>(x1, ln2_w, ln2_b, hh, hl);
    // 8. FC + GELU -> fc pair
    gemm_bf16x3<2><<<dim3(4*CC/128, NROWS/128), 256, GSMEM>>>(
        hh, hl, wfh, wfl, b_fc, nullptr, nullptr, fch, fcl, 4*CC, CC);
    // 9. mproj + residual -> out
    gemm_bf16x3<1><<<dim3(CC/128, NROWS/128), 256, GSMEM>>>(
        fch, fcl, wmh, wml, b_mproj, x1, out, nullptr, nullptr, CC, 4*CC);
}

// round 4
// speedup vs baseline: 2.5527x; 1.4816x over previous
#include <cuda_runtime.h>
#include <cuda_bf16.h>
#include <math.h>
#include <stdint.h>

#define BB 2
#define TT 2048
#define CC 1024
#define HH 16
#define DH 64
#define NROWS (BB*TT)          // 4096

// ================= static scratch =================
__device__ float g_xn [NROWS*CC];
__device__ float g_y  [NROWS*CC];
__device__ float g_x1 [NROWS*CC];

__device__ __nv_bfloat16 g_xt_h[NROWS*CC],   g_xt_l[NROWS*CC];
__device__ __nv_bfloat16 g_y_h [NROWS*CC],   g_y_l [NROWS*CC];
__device__ __nv_bfloat16 g_h_h [NROWS*CC],   g_h_l [NROWS*CC];
__device__ __nv_bfloat16 g_fc_h[NROWS*4*CC], g_fc_l[NROWS*4*CC];

// attention Q/K/V in [B,H,T,D] bf16 hi/lo
__device__ __nv_bfloat16 g_qh[NROWS*CC], g_ql[NROWS*CC];
__device__ __nv_bfloat16 g_kh[NROWS*CC], g_kl[NROWS*CC];
__device__ __nv_bfloat16 g_vh[NROWS*CC], g_vl[NROWS*CC];

// transposed split weights: [N, K] bf16
__device__ __nv_bfloat16 g_wattn_h [3*CC*CC], g_wattn_l [3*CC*CC];
__device__ __nv_bfloat16 g_waproj_h[CC*CC],   g_waproj_l[CC*CC];
__device__ __nv_bfloat16 g_wfc_h   [4*CC*CC], g_wfc_l   [4*CC*CC];
__device__ __nv_bfloat16 g_wmproj_h[CC*4*CC], g_wmproj_l[CC*4*CC];

#define QSCALE 0.18033688011112042f   // 0.125 * log2(e)

// ================= helpers =================
__device__ __forceinline__ uint32_t smem_u32(const void* p) {
    uint32_t a;
    asm("{ .reg .u64 t; cvta.to.shared.u64 t, %1; cvt.u32.u64 %0, t; }" : "=r"(a) : "l"(p));
    return a;
}
#define SWZ(x) ((x) ^ (((x) >> 3) & 0x70))

__device__ __forceinline__ void cp16(uint32_t sa, const void* g) {
    asm volatile("cp.async.cg.shared.global [%0], [%1], 16;" :: "r"(sa), "l"(g));
}
#define CP_COMMIT() asm volatile("cp.async.commit_group;" ::: "memory")
template <int N> __device__ __forceinline__ void cpwait() {
    asm volatile("cp.async.wait_group %0;" :: "n"(N) : "memory");
}

__device__ __forceinline__ void ldsm4(uint32_t& r0, uint32_t& r1, uint32_t& r2, uint32_t& r3, uint32_t a) {
    asm volatile("ldmatrix.sync.aligned.m8n8.x4.shared.b16 {%0,%1,%2,%3}, [%4];"
        : "=r"(r0), "=r"(r1), "=r"(r2), "=r"(r3) : "r"(a));
}
__device__ __forceinline__ void ldsm4t(uint32_t& r0, uint32_t& r1, uint32_t& r2, uint32_t& r3, uint32_t a) {
    asm volatile("ldmatrix.sync.aligned.m8n8.x4.trans.shared.b16 {%0,%1,%2,%3}, [%4];"
        : "=r"(r0), "=r"(r1), "=r"(r2), "=r"(r3) : "r"(a));
}
__device__ __forceinline__ void mma16816(float* c, const uint32_t* a, const uint32_t* b) {
    asm volatile("mma.sync.aligned.m16n8k16.row.col.f32.bf16.bf16.f32 "
        "{%0,%1,%2,%3}, {%4,%5,%6,%7}, {%8,%9}, {%0,%1,%2,%3};"
        : "+f"(c[0]), "+f"(c[1]), "+f"(c[2]), "+f"(c[3])
        : "r"(a[0]), "r"(a[1]), "r"(a[2]), "r"(a[3]), "r"(b[0]), "r"(b[1]));
}
__device__ __forceinline__ float ex2f(float x) {
    float r; asm("ex2.approx.f32 %0, %1;" : "=f"(r) : "f"(x)); return r;
}
__device__ __forceinline__ void split2(float v, __nv_bfloat16& h, __nv_bfloat16& l) {
    h = __float2bfloat16(v);
    l = __float2bfloat16(v - __bfloat162float(h));
}
__device__ __forceinline__ uint32_t pack2(__nv_bfloat16 a, __nv_bfloat16 b) {
    __nv_bfloat162 t(a, b); return *reinterpret_cast<uint32_t*>(&t);
}

// ================= block reduce (256 thr) =================
__device__ __forceinline__ void block_reduce(float* vals, int n, float* scr) {
    int tid = threadIdx.x, lane = tid & 31, wid = tid >> 5;
    for (int k = 0; k < n; k++) {
        float v = vals[k];
        #pragma unroll
        for (int o = 16; o; o >>= 1) v += __shfl_xor_sync(0xffffffffu, v, o);
        if (lane == 0) scr[k*8 + wid] = v;
    }
    __syncthreads();
    if (tid == 0) {
        for (int k = 0; k < n; k++) {
            float s = 0.f;
            #pragma unroll
            for (int w = 0; w < 8; w++) s += scr[k*8 + w];
            scr[24 + k] = s;
        }
    }
    __syncthreads();
    for (int k = 0; k < n; k++) vals[k] = scr[24 + k];
    __syncthreads();
}

// ================= LayerNorm (fp32 out) =================
__global__ void ln_kernel(const float* __restrict__ x, const float* __restrict__ w,
                          const float* __restrict__ b, float* __restrict__ out) {
    __shared__ float scr[32];
    int row = blockIdx.x;
    const float* xr = x + (size_t)row * CC;
    float* orow = out + (size_t)row * CC;
    int tid = threadIdx.x;
    float v2[2] = {0.f, 0.f};
    for (int i = tid; i < CC; i += 256) { float v = xr[i]; v2[0] += v; v2[1] += v*v; }
    block_reduce(v2, 2, scr);
    float mean = v2[0] * (1.0f/CC);
    float var  = v2[1] * (1.0f/CC) - mean*mean;
    float inv  = rsqrtf(var + 1e-5f);
    for (int i = tid; i < CC; i += 256)
        orow[i] = (xr[i] - mean) * inv * w[i] + b[i];
}

// ================= LayerNorm (bf16 pair out) =================
__global__ void ln_pair_kernel(const float* __restrict__ x, const float* __restrict__ w,
                               const float* __restrict__ b,
                               __nv_bfloat16* __restrict__ oh, __nv_bfloat16* __restrict__ ol) {
    __shared__ float scr[32];
    int row = blockIdx.x;
    const float* xr = x + (size_t)row * CC;
    int tid = threadIdx.x;
    float v2[2] = {0.f, 0.f};
    for (int i = tid; i < CC; i += 256) { float v = xr[i]; v2[0] += v; v2[1] += v*v; }
    block_reduce(v2, 2, scr);
    float mean = v2[0] * (1.0f/CC);
    float var  = v2[1] * (1.0f/CC) - mean*mean;
    float inv  = rsqrtf(var + 1e-5f);
    size_t base = (size_t)row * CC;
    for (int i = tid; i < CC; i += 256) {
        float v = (xr[i] - mean) * inv * w[i] + b[i];
        __nv_bfloat16 h, l; split2(v, h, l);
        oh[base + i] = h; ol[base + i] = l;
    }
}

// ================= logmap -> bf16 pair =================
__global__ void logmap_kernel(const float* __restrict__ xn,
                              __nv_bfloat16* __restrict__ oh, __nv_bfloat16* __restrict__ ol) {
    __shared__ float scr[32];
    __shared__ float ms[CC];
    int row = blockIdx.x;
    int t = row & (TT - 1);
    const float* u = xn + (size_t)row * CC;
    const float* a = (t == 0) ? nullptr : xn + (size_t)(row - 1) * CC;
    int tid = threadIdx.x;

    float v3[3] = {0.f, 0.f, 0.f};
    for (int i = tid; i < CC; i += 256) {
        float ui = u[i];
        float ai = a ? a[i] : 0.f;
        v3[0] += ai*ai; v3[1] += ui*ui; v3[2] += ai*ui;
    }
    block_reduce(v3, 3, scr);
    float an2 = v3[0], un2 = v3[1], ipau = v3[2];

    float coefX = 1.f - 2.f*ipau + un2;
    float coefU = 1.f - an2;
    float den   = 1.f - 2.f*ipau + an2*un2;
    float rden  = 1.f / den;

    float mn2v[1] = {0.f};
    for (int i = tid; i < CC; i += 256) {
        float ai = a ? a[i] : 0.f;
        float mi = (coefU * u[i] - coefX * ai) * rden;
        ms[i] = mi;
        mn2v[0] += mi*mi;
    }
    block_reduce(mn2v, 1, scr);
    float mn = sqrtf(mn2v[0]);
    float cf = 1.f + an2;
    float arg = fminf(sqrtf(mn), 0.999f);
    float scale = cf * atanhf(arg) / mn;
    size_t base = (size_t)row * CC;
    for (int i = tid; i < CC; i += 256) {
        __nv_bfloat16 h, l; split2(scale * ms[i], h, l);
        oh[base + i] = h; ol[base + i] = l;
    }
}

// ================= expmap: y fp32 -> bf16 pair =================
__global__ void expmap_kernel(const float* __restrict__ xn, const float* __restrict__ y,
                              __nv_bfloat16* __restrict__ oh, __nv_bfloat16* __restrict__ ol) {
    __shared__ float scr[32];
    int row = blockIdx.x;
    int t = row & (TT - 1);
    const float* xr = (t == 0) ? nullptr : xn + (size_t)(row - 1) * CC;
    const float* v = y + (size_t)row * CC;
    int tid = threadIdx.x;

    float v3[3] = {0.f, 0.f, 0.f};
    for (int i = tid; i < CC; i += 256) {
        float vi = v[i];
        float xi = xr ? xr[i] : 0.f;
        v3[0] += xi*xi; v3[1] += vi*vi; v3[2] += xi*vi;
    }
    block_reduce(v3, 3, scr);
    float refn2 = v3[0], vn2 = v3[1], xv = v3[2];

    float lam = 2.f / (1.f + refn2);
    float vn  = sqrtf(vn2);
    float th  = tanhf(sqrtf(lam * vn2 * 0.5f));
    float ss  = th / vn;
    float secn2 = th * th;
    float ipxs  = ss * xv;
    float coefX = 1.f + 2.f*ipxs + secn2;
    float coefY = (1.f - refn2) * ss;
    float rden  = 1.f / (1.f + 2.f*ipxs + refn2*secn2);
    size_t base = (size_t)row * CC;
    for (int i = tid; i < CC; i += 256) {
        float xi = xr ? xr[i] : 0.f;
        float r = (coefX * xi + coefY * v[i]) * rden;
        __nv_bfloat16 h, l; split2(r, h, l);
        oh[base + i] = h; ol[base + i] = l;
    }
}

// ================= weight transpose + split =================
__global__ void wsplit_kernel(const float* __restrict__ W,
                              __nv_bfloat16* __restrict__ Wh, __nv_bfloat16* __restrict__ Wl,
                              int K, int N) {
    __shared__ float t[32][33];
    int n0 = blockIdx.x * 32, k0 = blockIdx.y * 32;
    int tx = threadIdx.x, ty = threadIdx.y;   // 32 x 8
    #pragma unroll
    for (int j = 0; j < 32; j += 8)
        t[ty + j][tx] = W[(size_t)(k0 + ty + j) * N + n0 + tx];
    __syncthreads();
    #pragma unroll
    for (int j = 0; j < 32; j += 8) {
        float v = t[tx][ty + j];
        __nv_bfloat16 h, l; split2(v, h, l);
        size_t o = (size_t)(n0 + ty + j) * K + k0 + tx;
        Wh[o] = h; Wl[o] = l;
    }
}

// ================= HMMA bf16x3 GEMM =================
// EPI 0: fp32 out   EPI 1: fp32 + residual   EPI 2: gelu -> bf16 pair
// EPI 3: qkv -> Q(scaled)/K/V bf16 pairs in [B,H,T,D]
#define TILEB 16384
#define STAGEB (4*TILEB)
#define GSMEM (2*STAGEB)

__device__ __forceinline__ void load_tile(uint32_t sdst, const __nv_bfloat16* g,
                                          int row0, int Kd, int k0, int tid) {
    const __nv_bfloat16* base = g + (size_t)row0 * Kd + k0;
    #pragma unroll
    for (int i = 0; i < 4; i++) {
        int idx = tid * 4 + i;
        int r = idx >> 3, gc = idx & 7;
        uint32_t so = sdst + SWZ((uint32_t)(r * 128 + gc * 16));
        cp16(so, base + (size_t)r * Kd + gc * 8);
    }
}

template<int EPI>
__global__ void __launch_bounds__(256, 1) gemm_bf16x3(
    const __nv_bfloat16* __restrict__ Ah, const __nv_bfloat16* __restrict__ Al,
    const __nv_bfloat16* __restrict__ Bh, const __nv_bfloat16* __restrict__ Bl,
    const float* __restrict__ bias, const float* __restrict__ res,
    float* __restrict__ Cf, __nv_bfloat16* __restrict__ Coh, __nv_bfloat16* __restrict__ Col,
    __nv_bfloat16* __restrict__ Ckh, __nv_bfloat16* __restrict__ Ckl,
    __nv_bfloat16* __restrict__ Cvh, __nv_bfloat16* __restrict__ Cvl,
    int Nd, int Kd)
{
    extern __shared__ __align__(1024) char smem[];
    uint32_t sb = smem_u32(smem);
    int tid = threadIdx.x, wid = tid >> 5, lane = tid & 31;
    int wm = wid >> 2, wn = wid & 3;
    int bm = blockIdx.y * 128, bn = blockIdx.x * 128;

    float acc[4][4][4];
    #pragma unroll
    for (int mt = 0; mt < 4; mt++)
        #pragma unroll
        for (int nt = 0; nt < 4; nt++)
            #pragma unroll
            for (int r = 0; r < 4; r++) acc[mt][nt][r] = 0.f;

    int nch = Kd >> 6;

    #pragma unroll
    for (int s = 0; s < 2; s++) {
        uint32_t st = sb + s * STAGEB;
        int k0 = s * 64;
        load_tile(st,           Ah, bm, Kd, k0, tid);
        load_tile(st +   TILEB, Al, bm, Kd, k0, tid);
        load_tile(st + 2*TILEB, Bh, bn, Kd, k0, tid);
        load_tile(st + 3*TILEB, Bl, bn, Kd, k0, tid);
        CP_COMMIT();
    }

    int grp = lane >> 3, rw = lane & 7;
    int a_row = (grp & 1) * 8 + rw;
    int a_kb  = (grp >> 1) * 16;
    int b_row = (grp >> 1) * 8 + rw;
    int b_kb  = (grp & 1) * 16;

    for (int c = 0; c < nch; c++) {
        if (c + 1 < nch) cpwait<1>(); else cpwait<0>();
        __syncthreads();
        uint32_t st = sb + (c & 1) * STAGEB;
        uint32_t Ahs = st, Als = st + TILEB, Bhs = st + 2*TILEB, Bls = st + 3*TILEB;

        #pragma unroll
        for (int kk = 0; kk < 4; kk++) {
            uint32_t ah[4][4], al[4][4], bh[4][2], bl[4][2];
            #pragma unroll
            for (int mt = 0; mt < 4; mt++) {
                uint32_t off = SWZ((uint32_t)((wm*64 + mt*16 + a_row) * 128 + kk*32 + a_kb));
                ldsm4(ah[mt][0], ah[mt][1], ah[mt][2], ah[mt][3], Ahs + off);
                ldsm4(al[mt][0], al[mt][1], al[mt][2], al[mt][3], Als + off);
            }
            #pragma unroll
            for (int p = 0; p < 2; p++) {
                uint32_t off = SWZ((uint32_t)((wn*32 + p*16 + b_row) * 128 + kk*32 + b_kb));
                ldsm4(bh[2*p][0], bh[2*p][1], bh[2*p+1][0], bh[2*p+1][1], Bhs + off);
                ldsm4(bl[2*p][0], bl[2*p][1], bl[2*p+1][0], bl[2*p+1][1], Bls + off);
            }
            #pragma unroll
            for (int mt = 0; mt < 4; mt++)
                #pragma unroll
                for (int nt = 0; nt < 4; nt++) {
                    mma16816(acc[mt][nt], ah[mt], bh[nt]);
                    mma16816(acc[mt][nt], ah[mt], bl[nt]);
                    mma16816(acc[mt][nt], al[mt], bh[nt]);
                }
        }
        __syncthreads();
        int cn = c + 2;
        if (cn < nch) {
            int k0 = cn * 64;
            load_tile(st,           Ah, bm, Kd, k0, tid);
            load_tile(st +   TILEB, Al, bm, Kd, k0, tid);
            load_tile(st + 2*TILEB, Bh, bn, Kd, k0, tid);
            load_tile(st + 3*TILEB, Bl, bn, Kd, k0, tid);
            CP_COMMIT();
        }
    }

    // epilogue
    int r0 = lane >> 2, c0 = (lane & 3) * 2;
    #pragma unroll
    for (int mt = 0; mt < 4; mt++) {
        #pragma unroll
        for (int nt = 0; nt < 4; nt++) {
            int col = bn + wn*32 + nt*8 + c0;
            float b0 = bias[col], b1 = bias[col + 1];
            #pragma unroll
            for (int half = 0; half < 2; half++) {
                int row = bm + wm*64 + mt*16 + r0 + half*8;
                float v0 = acc[mt][nt][half*2]     + b0;
                float v1 = acc[mt][nt][half*2 + 1] + b1;
                if (EPI == 3) {
                    int part = col >> 10;
                    int head = (col >> 6) & 15;
                    int d    = col & 63;
                    if (part == 0) { v0 *= QSCALE; v1 *= QSCALE; }
                    __nv_bfloat16 h0, l0, h1, l1;
                    split2(v0, h0, l0); split2(v1, h1, l1);
                    size_t off = ((((size_t)(row >> 11)) * 16 + head) * TT + (row & 2047)) * 64 + d;
                    __nv_bfloat16* Dh = (part == 0) ? Coh : (part == 1) ? Ckh : Cvh;
                    __nv_bfloat16* Dl = (part == 0) ? Col : (part == 1) ? Ckl : Cvl;
                    *reinterpret_cast<__nv_bfloat162*>(Dh + off) = __nv_bfloat162(h0, h1);
                    *reinterpret_cast<__nv_bfloat162*>(Dl + off) = __nv_bfloat162(l0, l1);
                } else {
                    size_t off = (size_t)row * Nd + col;
                    if (EPI == 2) {
                        v0 = v0 * normcdff(v0);
                        v1 = v1 * normcdff(v1);
                        __nv_bfloat16 h0, l0, h1, l1;
                        split2(v0, h0, l0); split2(v1, h1, l1);
                        *reinterpret_cast<__nv_bfloat162*>(Coh + off) = __nv_bfloat162(h0, h1);
                        *reinterpret_cast<__nv_bfloat162*>(Col + off) = __nv_bfloat162(l0, l1);
                    } else {
                        if (EPI == 1) { v0 += res[off]; v1 += res[off + 1]; }
                        *reinterpret_cast<float2*>(Cf + off) = make_float2(v0, v1);
                    }
                }
            }
        }
    }
}

// ================= HMMA bf16x3 flash attention =================
// 256 thr / 8 warps, BQ=128 (16 rows per warp), BK=64, double-buffered K/V h/l.
#define AT_SMEM (32768 + 2*32768)   // Q(32K) + 2 KV stages (32K each)

__device__ __forceinline__ void load_kv(uint32_t st,
        const __nv_bfloat16* khp, const __nv_bfloat16* klp,
        const __nv_bfloat16* vhp, const __nv_bfloat16* vlp, int kt, int tid) {
    int k0 = kt * 64;
    #pragma unroll
    for (int i = 0; i < 2; i++) {
        int idx = tid * 2 + i;
        int r = idx >> 3, gc = idx & 7;
        uint32_t off = SWZ((uint32_t)(r * 128 + gc * 16));
        size_t g = (size_t)(k0 + r) * 64 + gc * 8;
        cp16(st + off,         khp + g);
        cp16(st + 8192 + off,  klp + g);
        cp16(st + 16384 + off, vhp + g);
        cp16(st + 24576 + off, vlp + g);
    }
}

__global__ void __launch_bounds__(256, 1) attn_hmma(
    const __nv_bfloat16* __restrict__ Qh, const __nv_bfloat16* __restrict__ Ql,
    const __nv_bfloat16* __restrict__ Kh, const __nv_bfloat16* __restrict__ Kl,
    const __nv_bfloat16* __restrict__ Vh, const __nv_bfloat16* __restrict__ Vl,
    float* __restrict__ y)
{
    extern __shared__ __align__(1024) char smem[];
    uint32_t sb = smem_u32(smem);
    int tid = threadIdx.x, wid = tid >> 5, lane = tid & 31;
    int bhx = blockIdx.y, b = bhx >> 4, h = bhx & 15;
    int q0 = blockIdx.x * 128;
    size_t hb = (size_t)bhx * TT * DH;
    const __nv_bfloat16 *qhp = Qh + hb, *qlp = Ql + hb;
    const __nv_bfloat16 *khp = Kh + hb, *klp = Kl + hb;
    const __nv_bfloat16 *vhp = Vh + hb, *vlp = Vl + hb;

    uint32_t sQh = sb, sQl = sb + 16384;
    uint32_t stg0 = sb + 32768, stg1 = sb + 65536;

    int ntiles = 2 * (blockIdx.x + 1);

    // prologue: Q + KV0 (group 0), KV1 (group 1)
    load_tile(sQh, qhp, q0, 64, 0, tid);
    load_tile(sQl, qlp, q0, 64, 0, tid);
    load_kv(stg0, khp, klp, vhp, vlp, 0, tid);
    CP_COMMIT();
    if (ntiles > 1) { load_kv(stg1, khp, klp, vhp, vlp, 1, tid); CP_COMMIT(); }
    if (ntiles > 1) cpwait<1>(); else cpwait<0>();
    __syncthreads();

    int grp = lane >> 3, rw = lane & 7;
    int a_row = (grp & 1) * 8 + rw, a_kb = (grp >> 1) * 16;
    int b_row = (grp >> 1) * 8 + rw, b_kb = (grp & 1) * 16;
    int v_row = (grp & 1) * 8 + rw,  v_db = (grp >> 1) * 16;

    // Q fragments in registers
    uint32_t qfh[4][4], qfl[4][4];
    #pragma unroll
    for (int kk = 0; kk < 4; kk++) {
        uint32_t off = SWZ((uint32_t)((wid*16 + a_row) * 128 + kk*32 + a_kb));
        ldsm4(qfh[kk][0], qfh[kk][1], qfh[kk][2], qfh[kk][3], sQh + off);
        ldsm4(qfl[kk][0], qfl[kk][1], qfl[kk][2], qfl[kk][3], sQl + off);
    }

    float o[8][4];
    #pragma unroll
    for (int nt = 0; nt < 8; nt++)
        #pragma unroll
        for (int r = 0; r < 4; r++) o[nt][r] = 0.f;
    float m0 = -1e30f, m1 = -1e30f, l0 = 0.f, l1 = 0.f;

    int qr0 = q0 + wid*16 + (lane >> 2);   // this thread's row (r0); r1 = qr0+8
    int kc0 = (lane & 3) * 2;

    for (int kt = 0; kt < ntiles; kt++) {
        if (kt > 0) {
            if (kt + 1 < ntiles) cpwait<1>(); else cpwait<0>();
            __syncthreads();
        }
        uint32_t st = (kt & 1) ? stg1 : stg0;
        int k0 = kt * 64;
        if (k0 <= q0 + wid*16 + 15) {
            uint32_t sKh = st, sKl = st + 8192, sVh = st + 16384, sVl = st + 24576;
            float s[8][4];
            #pragma unroll
            for (int nt = 0; nt < 8; nt++)
                #pragma unroll
                for (int r = 0; r < 4; r++) s[nt][r] = 0.f;

            #pragma unroll
            for (int kk = 0; kk < 4; kk++) {
                uint32_t bhf[8][2], blf[8][2];
                #pragma unroll
                for (int p = 0; p < 4; p++) {
                    uint32_t off = SWZ((uint32_t)((p*16 + b_row) * 128 + kk*32 + b_kb));
                    ldsm4(bhf[2*p][0], bhf[2*p][1], bhf[2*p+1][0], bhf[2*p+1][1], sKh + off);
                    ldsm4(blf[2*p][0], blf[2*p][1], blf[2*p+1][0], blf[2*p+1][1], sKl + off);
                }
                #pragma unroll
                for (int nt = 0; nt < 8; nt++) {
                    mma16816(s[nt], qfh[kk], bhf[nt]);
                    mma16816(s[nt], qfh[kk], blf[nt]);
                    mma16816(s[nt], qfl[kk], bhf[nt]);
                }
            }

            // causal mask
            if (k0 + 63 > qr0) {
                #pragma unroll
                for (int nt = 0; nt < 8; nt++) {
                    int kg = k0 + nt*8 + kc0;
                    if (kg     > qr0)     s[nt][0] = -1e30f;
                    if (kg + 1 > qr0)     s[nt][1] = -1e30f;
                    if (kg     > qr0 + 8) s[nt][2] = -1e30f;
                    if (kg + 1 > qr0 + 8) s[nt][3] = -1e30f;
                }
            }

            // online softmax (log2 domain; Q pre-scaled)
            float t0 = -1e30f, t1 = -1e30f;
            #pragma unroll
            for (int nt = 0; nt < 8; nt++) {
                t0 = fmaxf(t0, fmaxf(s[nt][0], s[nt][1]));
                t1 = fmaxf(t1, fmaxf(s[nt][2], s[nt][3]));
            }
            t0 = fmaxf(t0, __shfl_xor_sync(0xffffffffu, t0, 1));
            t0 = fmaxf(t0, __shfl_xor_sync(0xffffffffu, t0, 2));
            t1 = fmaxf(t1, __shfl_xor_sync(0xffffffffu, t1, 1));
            t1 = fmaxf(t1, __shfl_xor_sync(0xffffffffu, t1, 2));
            float mn0 = fmaxf(m0, t0), mn1 = fmaxf(m1, t1);
            float al0 = ex2f(m0 - mn0), al1 = ex2f(m1 - mn1);
            m0 = mn0; m1 = mn1;

            float ps0 = 0.f, ps1 = 0.f;
            uint32_t pah[4][4], pal[4][4];
            #pragma unroll
            for (int nt = 0; nt < 8; nt++) {
                float p0 = ex2f(s[nt][0] - m0), p1 = ex2f(s[nt][1] - m0);
                float p2 = ex2f(s[nt][2] - m1), p3 = ex2f(s[nt][3] - m1);
                ps0 += p0 + p1; ps1 += p2 + p3;
                __nv_bfloat16 h0,g0,h1,g1,h2,g2,h3,g3;
                split2(p0,h0,g0); split2(p1,h1,g1); split2(p2,h2,g2); split2(p3,h3,g3);
                int jj = nt >> 1, rb = (nt & 1) * 2;
                pah[jj][rb]   = pack2(h0, h1);
                pah[jj][rb+1] = pack2(h2, h3);
                pal[jj][rb]   = pack2(g0, g1);
                pal[jj][rb+1] = pack2(g2, g3);
            }
            ps0 += __shfl_xor_sync(0xffffffffu, ps0, 1);
            ps0 += __shfl_xor_sync(0xffffffffu, ps0, 2);
            ps1 += __shfl_xor_sync(0xffffffffu, ps1, 1);
            ps1 += __shfl_xor_sync(0xffffffffu, ps1, 2);
            l0 = al0 * l0 + ps0;
            l1 = al1 * l1 + ps1;
            #pragma unroll
            for (int nt = 0; nt < 8; nt++) {
                o[nt][0] *= al0; o[nt][1] *= al0;
                o[nt][2] *= al1; o[nt][3] *= al1;
            }

            // O += P @ V
            #pragma unroll
            for (int j = 0; j < 4; j++) {
                uint32_t vhf[8][2], vlf[8][2];
                #pragma unroll
                for (int p = 0; p < 4; p++) {
                    uint32_t off = SWZ((uint32_t)((j*16 + v_row) * 128 + p*32 + v_db));
                    ldsm4t(vhf[2*p][0], vhf[2*p][1], vhf[2*p+1][0], vhf[2*p+1][1], sVh + off);
                    ldsm4t(vlf[2*p][0], vlf[2*p][1], vlf[2*p+1][0], vlf[2*p+1][1], sVl + off);
                }
                #pragma unroll
                for (int nt = 0; nt < 8; nt++) {
                    mma16816(o[nt], pah[j], vhf[nt]);
                    mma16816(o[nt], pah[j], vlf[nt]);
                    mma16816(o[nt], pal[j], vhf[nt]);
                }
            }
        }
        __syncthreads();
        if (kt + 2 < ntiles) {
            load_kv((kt & 1) ? stg1 : stg0, khp, klp, vhp, vlp, kt + 2, tid);
            CP_COMMIT();
        }
    }

    // write out
    float rl0 = 1.f / l0, rl1 = 1.f / l1;
    size_t base0 = ((size_t)(b*TT + qr0) * CC) + h*64 + kc0;
    size_t base1 = base0 + (size_t)8 * CC;
    #pragma unroll
    for (int nt = 0; nt < 8; nt++) {
        *reinterpret_cast<float2*>(y + base0 + nt*8) = make_float2(o[nt][0]*rl0, o[nt][1]*rl0);
        *reinterpret_cast<float2*>(y + base1 + nt*8) = make_float2(o[nt][2]*rl1, o[nt][3]*rl1);
    }
}

// ================= launch =================
extern "C" void kernel_launch(void* const* d_in, const int* in_sizes, int n_in,
                              void* d_out, int out_size) {
    const float* x       = (const float*)d_in[0];
    const float* ln1_w   = (const float*)d_in[1];
    const float* ln1_b   = (const float*)d_in[2];
    const float* W_attn  = (const float*)d_in[3];
    const float* b_attn  = (const float*)d_in[4];
    const float* W_aproj = (const float*)d_in[5];
    const float* b_aproj = (const float*)d_in[6];
    const float* ln2_w   = (const float*)d_in[7];
    const float* ln2_b   = (const float*)d_in[8];
    const float* W_fc    = (const float*)d_in[9];
    const float* b_fc    = (const float*)d_in[10];
    const float* W_mproj = (const float*)d_in[11];
    const float* b_mproj = (const float*)d_in[12];
    float* out = (float*)d_out;

    float *xn, *y, *x1;
    __nv_bfloat16 *xth, *xtl, *yh, *yl, *hh, *hl, *fch, *fcl;
    __nv_bfloat16 *qh, *ql, *kh, *kl, *vh, *vl;
    __nv_bfloat16 *wah, *wal, *wph, *wpl, *wfh, *wfl, *wmh, *wml;
    cudaGetSymbolAddress((void**)&xn,  g_xn);
    cudaGetSymbolAddress((void**)&y,   g_y);
    cudaGetSymbolAddress((void**)&x1,  g_x1);
    cudaGetSymbolAddress((void**)&xth, g_xt_h); cudaGetSymbolAddress((void**)&xtl, g_xt_l);
    cudaGetSymbolAddress((void**)&yh,  g_y_h);  cudaGetSymbolAddress((void**)&yl,  g_y_l);
    cudaGetSymbolAddress((void**)&hh,  g_h_h);  cudaGetSymbolAddress((void**)&hl,  g_h_l);
    cudaGetSymbolAddress((void**)&fch, g_fc_h); cudaGetSymbolAddress((void**)&fcl, g_fc_l);
    cudaGetSymbolAddress((void**)&qh, g_qh); cudaGetSymbolAddress((void**)&ql, g_ql);
    cudaGetSymbolAddress((void**)&kh, g_kh); cudaGetSymbolAddress((void**)&kl, g_kl);
    cudaGetSymbolAddress((void**)&vh, g_vh); cudaGetSymbolAddress((void**)&vl, g_vl);
    cudaGetSymbolAddress((void**)&wah, g_wattn_h);  cudaGetSymbolAddress((void**)&wal, g_wattn_l);
    cudaGetSymbolAddress((void**)&wph, g_waproj_h); cudaGetSymbolAddress((void**)&wpl, g_waproj_l);
    cudaGetSymbolAddress((void**)&wfh, g_wfc_h);    cudaGetSymbolAddress((void**)&wfl, g_wfc_l);
    cudaGetSymbolAddress((void**)&wmh, g_wmproj_h); cudaGetSymbolAddress((void**)&wml, g_wmproj_l);

    cudaFuncSetAttribute(attn_hmma, cudaFuncAttributeMaxDynamicSharedMemorySize, AT_SMEM);
    cudaFuncSetAttribute(gemm_bf16x3<0>, cudaFuncAttributeMaxDynamicSharedMemorySize, GSMEM);
    cudaFuncSetAttribute(gemm_bf16x3<1>, cudaFuncAttributeMaxDynamicSharedMemorySize, GSMEM);
    cudaFuncSetAttribute(gemm_bf16x3<2>, cudaFuncAttributeMaxDynamicSharedMemorySize, GSMEM);
    cudaFuncSetAttribute(gemm_bf16x3<3>, cudaFuncAttributeMaxDynamicSharedMemorySize, GSMEM);

    dim3 tb(32, 8);
    wsplit_kernel<<<dim3(3*CC/32, CC/32), tb>>>(W_attn,  wah, wal, CC,   3*CC);
    wsplit_kernel<<<dim3(CC/32,   CC/32), tb>>>(W_aproj, wph, wpl, CC,   CC);
    wsplit_kernel<<<dim3(4*CC/32, CC/32), tb>>>(W_fc,    wfh, wfl, CC,   4*CC);
    wsplit_kernel<<<dim3(CC/32, 4*CC/32), tb>>>(W_mproj, wmh, wml, 4*CC, CC);

    // 1. LN1
    ln_kernel<<<NROWS, 256>>>(x, ln1_w, ln1_b, xn);
    // 2. logmap -> xt pair
    logmap_kernel<<<NROWS, 256>>>(xn, xth, xtl);
    // 3. QKV GEMM -> split Q/K/V in [B,H,T,D], Q pre-scaled for log2 softmax
    gemm_bf16x3<3><<<dim3(3*CC/128, NROWS/128), 256, GSMEM>>>(
        xth, xtl, wah, wal, b_attn, nullptr, nullptr,
        qh, ql, kh, kl, vh, vl, 3*CC, CC);
    // 4. attention (HMMA bf16x3 flash)
    attn_hmma<<<dim3(TT/128, BB*HH), 256, AT_SMEM>>>(qh, ql, kh, kl, vh, vl, y);
    // 5. expmap -> y pair
    expmap_kernel<<<NROWS, 256>>>(xn, y, yh, yl);
    // 6. aproj + residual -> x1 fp32
    gemm_bf16x3<1><<<dim3(CC/128, NROWS/128), 256, GSMEM>>>(
        yh, yl, wph, wpl, b_aproj, x, x1, nullptr, nullptr,
        nullptr, nullptr, nullptr, nullptr, CC, CC);
    // 7. LN2 -> h pair
    ln_pair_kernel<<<NROWS, 256>>>(x1, ln2_w, ln2_b, hh, hl);
    // 8. FC + GELU -> fc pair
    gemm_bf16x3<2><<<dim3(4*CC/128, NROWS/128), 256, GSMEM>>>(
        hh, hl, wfh, wfl, b_fc, nullptr, nullptr, fch, fcl,
        nullptr, nullptr, nullptr, nullptr, 4*CC, CC);
    // 9. mproj + residual -> out
    gemm_bf16x3<1><<<dim3(CC/128, NROWS/128), 256, GSMEM>>>(
        fch, fcl, wmh, wml, b_mproj, x1, out, nullptr, nullptr,
        nullptr, nullptr, nullptr, nullptr, CC, 4*CC);
}

// round 5
// speedup vs baseline: 3.2251x; 1.2634x over previous
#include <cuda_runtime.h>
#include <cuda_bf16.h>
#include <cuda_fp16.h>
#include <math.h>
#include <stdint.h>

#define BB 2
#define TT 2048
#define CC 1024
#define HH 16
#define DH 64
#define NROWS (BB*TT)          // 4096

// ================= static scratch =================
__device__ float g_xn [NROWS*CC];
__device__ float g_y  [NROWS*CC];
__device__ float g_x1 [NROWS*CC];

__device__ __nv_bfloat16 g_xt_h[NROWS*CC], g_xt_l[NROWS*CC];
__device__ __half        g_yh [NROWS*CC],  g_yl [NROWS*CC];
__device__ __half        g_hh [NROWS*CC],  g_hl [NROWS*CC];
__device__ __half        g_fch[NROWS*4*CC], g_fcl[NROWS*4*CC];

// attention Q/K bf16 hi/lo, V fp16 single, all [B,H,T,D]
__device__ __nv_bfloat16 g_qh[NROWS*CC], g_ql[NROWS*CC];
__device__ __nv_bfloat16 g_kh[NROWS*CC], g_kl[NROWS*CC];
__device__ __half        g_v [NROWS*CC];

// weights: qkv bf16 pair [N,K]; others fp16 single [N,K]
__device__ __nv_bfloat16 g_wattn_h[3*CC*CC], g_wattn_l[3*CC*CC];
__device__ __half g_waproj[CC*CC];
__device__ __half g_wfc   [4*CC*CC];
__device__ __half g_wmproj[CC*4*CC];

#define QSCALE 0.18033688011112042f   // 0.125 * log2(e)

// ================= helpers =================
__device__ __forceinline__ uint32_t smem_u32(const void* p) {
    uint32_t a;
    asm("{ .reg .u64 t; cvta.to.shared.u64 t, %1; cvt.u32.u64 %0, t; }" : "=r"(a) : "l"(p));
    return a;
}
#define SWZ(x) ((x) ^ (((x) >> 3) & 0x70))

__device__ __forceinline__ void cp16(uint32_t sa, const void* g) {
    asm volatile("cp.async.cg.shared.global [%0], [%1], 16;" :: "r"(sa), "l"(g));
}
#define CP_COMMIT() asm volatile("cp.async.commit_group;" ::: "memory")
template <int N> __device__ __forceinline__ void cpwait() {
    asm volatile("cp.async.wait_group %0;" :: "n"(N) : "memory");
}

__device__ __forceinline__ void ldsm4(uint32_t& r0, uint32_t& r1, uint32_t& r2, uint32_t& r3, uint32_t a) {
    asm volatile("ldmatrix.sync.aligned.m8n8.x4.shared.b16 {%0,%1,%2,%3}, [%4];"
        : "=r"(r0), "=r"(r1), "=r"(r2), "=r"(r3) : "r"(a));
}
__device__ __forceinline__ void ldsm4t(uint32_t& r0, uint32_t& r1, uint32_t& r2, uint32_t& r3, uint32_t a) {
    asm volatile("ldmatrix.sync.aligned.m8n8.x4.trans.shared.b16 {%0,%1,%2,%3}, [%4];"
        : "=r"(r0), "=r"(r1), "=r"(r2), "=r"(r3) : "r"(a));
}
__device__ __forceinline__ void mma_bf(float* c, const uint32_t* a, const uint32_t* b) {
    asm volatile("mma.sync.aligned.m16n8k16.row.col.f32.bf16.bf16.f32 "
        "{%0,%1,%2,%3}, {%4,%5,%6,%7}, {%8,%9}, {%0,%1,%2,%3};"
        : "+f"(c[0]), "+f"(c[1]), "+f"(c[2]), "+f"(c[3])
        : "r"(a[0]), "r"(a[1]), "r"(a[2]), "r"(a[3]), "r"(b[0]), "r"(b[1]));
}
__device__ __forceinline__ void mma_fp(float* c, const uint32_t* a, const uint32_t* b) {
    asm volatile("mma.sync.aligned.m16n8k16.row.col.f32.f16.f16.f32 "
        "{%0,%1,%2,%3}, {%4,%5,%6,%7}, {%8,%9}, {%0,%1,%2,%3};"
        : "+f"(c[0]), "+f"(c[1]), "+f"(c[2]), "+f"(c[3])
        : "r"(a[0]), "r"(a[1]), "r"(a[2]), "r"(a[3]), "r"(b[0]), "r"(b[1]));
}
__device__ __forceinline__ float ex2f(float x) {
    float r; asm("ex2.approx.f32 %0, %1;" : "=f"(r) : "f"(x)); return r;
}
__device__ __forceinline__ void split2(float v, __nv_bfloat16& h, __nv_bfloat16& l) {
    h = __float2bfloat16(v);
    l = __float2bfloat16(v - __bfloat162float(h));
}
__device__ __forceinline__ void split2h(float v, __half& h, __half& l) {
    h = __float2half(v);
    l = __float2half(v - __half2float(h));
}
__device__ __forceinline__ uint32_t pack2h(__half a, __half b) {
    __half2 t(a, b); return *reinterpret_cast<uint32_t*>(&t);
}

// ================= block reduce (256 thr) =================
__device__ __forceinline__ void block_reduce(float* vals, int n, float* scr) {
    int tid = threadIdx.x, lane = tid & 31, wid = tid >> 5;
    for (int k = 0; k < n; k++) {
        float v = vals[k];
        #pragma unroll
        for (int o = 16; o; o >>= 1) v += __shfl_xor_sync(0xffffffffu, v, o);
        if (lane == 0) scr[k*8 + wid] = v;
    }
    __syncthreads();
    if (tid == 0) {
        for (int k = 0; k < n; k++) {
            float s = 0.f;
            #pragma unroll
            for (int w = 0; w < 8; w++) s += scr[k*8 + w];
            scr[24 + k] = s;
        }
    }
    __syncthreads();
    for (int k = 0; k < n; k++) vals[k] = scr[24 + k];
    __syncthreads();
}

// ================= LayerNorm (fp32 out) =================
__global__ void ln_kernel(const float* __restrict__ x, const float* __restrict__ w,
                          const float* __restrict__ b, float* __restrict__ out) {
    __shared__ float scr[32];
    int row = blockIdx.x;
    const float* xr = x + (size_t)row * CC;
    float* orow = out + (size_t)row * CC;
    int tid = threadIdx.x;
    float v2[2] = {0.f, 0.f};
    for (int i = tid; i < CC; i += 256) { float v = xr[i]; v2[0] += v; v2[1] += v*v; }
    block_reduce(v2, 2, scr);
    float mean = v2[0] * (1.0f/CC);
    float var  = v2[1] * (1.0f/CC) - mean*mean;
    float inv  = rsqrtf(var + 1e-5f);
    for (int i = tid; i < CC; i += 256)
        orow[i] = (xr[i] - mean) * inv * w[i] + b[i];
}

// ================= LayerNorm (fp16 pair out) =================
__global__ void ln_pair_kernel(const float* __restrict__ x, const float* __restrict__ w,
                               const float* __restrict__ b,
                               __half* __restrict__ oh, __half* __restrict__ ol) {
    __shared__ float scr[32];
    int row = blockIdx.x;
    const float* xr = x + (size_t)row * CC;
    int tid = threadIdx.x;
    float v2[2] = {0.f, 0.f};
    for (int i = tid; i < CC; i += 256) { float v = xr[i]; v2[0] += v; v2[1] += v*v; }
    block_reduce(v2, 2, scr);
    float mean = v2[0] * (1.0f/CC);
    float var  = v2[1] * (1.0f/CC) - mean*mean;
    float inv  = rsqrtf(var + 1e-5f);
    size_t base = (size_t)row * CC;
    for (int i = tid; i < CC; i += 256) {
        float v = (xr[i] - mean) * inv * w[i] + b[i];
        __half h, l; split2h(v, h, l);
        oh[base + i] = h; ol[base + i] = l;
    }
}

// ================= logmap -> bf16 pair =================
__global__ void logmap_kernel(const float* __restrict__ xn,
                              __nv_bfloat16* __restrict__ oh, __nv_bfloat16* __restrict__ ol) {
    __shared__ float scr[32];
    __shared__ float ms[CC];
    int row = blockIdx.x;
    int t = row & (TT - 1);
    const float* u = xn + (size_t)row * CC;
    const float* a = (t == 0) ? nullptr : xn + (size_t)(row - 1) * CC;
    int tid = threadIdx.x;

    float v3[3] = {0.f, 0.f, 0.f};
    for (int i = tid; i < CC; i += 256) {
        float ui = u[i];
        float ai = a ? a[i] : 0.f;
        v3[0] += ai*ai; v3[1] += ui*ui; v3[2] += ai*ui;
    }
    block_reduce(v3, 3, scr);
    float an2 = v3[0], un2 = v3[1], ipau = v3[2];

    float coefX = 1.f - 2.f*ipau + un2;
    float coefU = 1.f - an2;
    float den   = 1.f - 2.f*ipau + an2*un2;
    float rden  = 1.f / den;

    float mn2v[1] = {0.f};
    for (int i = tid; i < CC; i += 256) {
        float ai = a ? a[i] : 0.f;
        float mi = (coefU * u[i] - coefX * ai) * rden;
        ms[i] = mi;
        mn2v[0] += mi*mi;
    }
    block_reduce(mn2v, 1, scr);
    float mn = sqrtf(mn2v[0]);
    float cf = 1.f + an2;
    float arg = fminf(sqrtf(mn), 0.999f);
    float scale = cf * atanhf(arg) / mn;
    size_t base = (size_t)row * CC;
    for (int i = tid; i < CC; i += 256) {
        __nv_bfloat16 h, l; split2(scale * ms[i], h, l);
        oh[base + i] = h; ol[base + i] = l;
    }
}

// ================= expmap: y fp32 -> fp16 pair =================
__global__ void expmap_kernel(const float* __restrict__ xn, const float* __restrict__ y,
                              __half* __restrict__ oh, __half* __restrict__ ol) {
    __shared__ float scr[32];
    int row = blockIdx.x;
    int t = row & (TT - 1);
    const float* xr = (t == 0) ? nullptr : xn + (size_t)(row - 1) * CC;
    const float* v = y + (size_t)row * CC;
    int tid = threadIdx.x;

    float v3[3] = {0.f, 0.f, 0.f};
    for (int i = tid; i < CC; i += 256) {
        float vi = v[i];
        float xi = xr ? xr[i] : 0.f;
        v3[0] += xi*xi; v3[1] += vi*vi; v3[2] += xi*vi;
    }
    block_reduce(v3, 3, scr);
    float refn2 = v3[0], vn2 = v3[1], xv = v3[2];

    float lam = 2.f / (1.f + refn2);
    float vn  = sqrtf(vn2);
    float th  = tanhf(sqrtf(lam * vn2 * 0.5f));
    float ss  = th / vn;
    float secn2 = th * th;
    float ipxs  = ss * xv;
    float coefX = 1.f + 2.f*ipxs + secn2;
    float coefY = (1.f - refn2) * ss;
    float rden  = 1.f / (1.f + 2.f*ipxs + refn2*secn2);
    size_t base = (size_t)row * CC;
    for (int i = tid; i < CC; i += 256) {
        float xi = xr ? xr[i] : 0.f;
        float r = (coefX * xi + coefY * v[i]) * rden;
        __half h, l; split2h(r, h, l);
        oh[base + i] = h; ol[base + i] = l;
    }
}

// ================= weight transpose kernels =================
__global__ void wsplit_kernel(const float* __restrict__ W,
                              __nv_bfloat16* __restrict__ Wh, __nv_bfloat16* __restrict__ Wl,
                              int K, int N) {
    __shared__ float t[32][33];
    int n0 = blockIdx.x * 32, k0 = blockIdx.y * 32;
    int tx = threadIdx.x, ty = threadIdx.y;
    #pragma unroll
    for (int j = 0; j < 32; j += 8)
        t[ty + j][tx] = W[(size_t)(k0 + ty + j) * N + n0 + tx];
    __syncthreads();
    #pragma unroll
    for (int j = 0; j < 32; j += 8) {
        float v = t[tx][ty + j];
        __nv_bfloat16 h, l; split2(v, h, l);
        size_t o = (size_t)(n0 + ty + j) * K + k0 + tx;
        Wh[o] = h; Wl[o] = l;
    }
}

__global__ void wtrans_h_kernel(const float* __restrict__ W, __half* __restrict__ Wt,
                                int K, int N) {
    __shared__ float t[32][33];
    int n0 = blockIdx.x * 32, k0 = blockIdx.y * 32;
    int tx = threadIdx.x, ty = threadIdx.y;
    #pragma unroll
    for (int j = 0; j < 32; j += 8)
        t[ty + j][tx] = W[(size_t)(k0 + ty + j) * N + n0 + tx];
    __syncthreads();
    #pragma unroll
    for (int j = 0; j < 32; j += 8)
        Wt[(size_t)(n0 + ty + j) * K + k0 + tx] = __float2half(t[tx][ty + j]);
}

// ================= shared tile loader (any 16-bit type, [rows,K] row-major) =================
#define TILEB 16384
__device__ __forceinline__ void load_tile(uint32_t sdst, const void* gv,
                                          int row0, int Kd, int k0, int tid) {
    const __nv_bfloat16* base = (const __nv_bfloat16*)gv + (size_t)row0 * Kd + k0;
    #pragma unroll
    for (int i = 0; i < 4; i++) {
        int idx = tid * 4 + i;
        int r = idx >> 3, gc = idx & 7;
        uint32_t so = sdst + SWZ((uint32_t)(r * 128 + gc * 16));
        cp16(so, base + (size_t)r * Kd + gc * 8);
    }
}

// ================= QKV GEMM: bf16x3, 3-stage, epilogue -> Q/K pairs + V fp16 =================
#define QSTAGEB (4*TILEB)          // Ah, Al, Bh, Bl
#define QGSMEM (3*QSTAGEB)         // 196608

__global__ void __launch_bounds__(256, 1) gemm_qkv(
    const __nv_bfloat16* __restrict__ Ah, const __nv_bfloat16* __restrict__ Al,
    const __nv_bfloat16* __restrict__ Bh, const __nv_bfloat16* __restrict__ Bl,
    const float* __restrict__ bias,
    __nv_bfloat16* __restrict__ Cqh, __nv_bfloat16* __restrict__ Cql,
    __nv_bfloat16* __restrict__ Ckh, __nv_bfloat16* __restrict__ Ckl,
    __half* __restrict__ Cv)
{
    const int Kd = CC;
    extern __shared__ __align__(1024) char smem[];
    uint32_t sb = smem_u32(smem);
    int tid = threadIdx.x, wid = tid >> 5, lane = tid & 31;
    int wm = wid >> 2, wn = wid & 3;
    int bm = blockIdx.y * 128, bn = blockIdx.x * 128;

    float acc[4][4][4];
    #pragma unroll
    for (int mt = 0; mt < 4; mt++)
        #pragma unroll
        for (int nt = 0; nt < 4; nt++)
            #pragma unroll
            for (int r = 0; r < 4; r++) acc[mt][nt][r] = 0.f;

    const int nch = Kd >> 6;   // 16

    #pragma unroll
    for (int s = 0; s < 3; s++) {
        uint32_t st = sb + s * QSTAGEB;
        int k0 = s * 64;
        load_tile(st,           Ah, bm, Kd, k0, tid);
        load_tile(st +   TILEB, Al, bm, Kd, k0, tid);
        load_tile(st + 2*TILEB, Bh, bn, Kd, k0, tid);
        load_tile(st + 3*TILEB, Bl, bn, Kd, k0, tid);
        CP_COMMIT();
    }

    int grp = lane >> 3, rw = lane & 7;
    int a_row = (grp & 1) * 8 + rw;
    int a_kb  = (grp >> 1) * 16;
    int b_row = (grp >> 1) * 8 + rw;
    int b_kb  = (grp & 1) * 16;

    for (int c = 0; c < nch; c++) {
        int rem = nch - 1 - c;
        if (rem >= 2) cpwait<2>(); else if (rem == 1) cpwait<1>(); else cpwait<0>();
        __syncthreads();
        uint32_t st = sb + (c % 3) * QSTAGEB;
        uint32_t Ahs = st, Als = st + TILEB, Bhs = st + 2*TILEB, Bls = st + 3*TILEB;

        #pragma unroll
        for (int kk = 0; kk < 4; kk++) {
            uint32_t ah[4][4], al[4][4], bh[4][2], bl[4][2];
            #pragma unroll
            for (int mt = 0; mt < 4; mt++) {
                uint32_t off = SWZ((uint32_t)((wm*64 + mt*16 + a_row) * 128 + kk*32 + a_kb));
                ldsm4(ah[mt][0], ah[mt][1], ah[mt][2], ah[mt][3], Ahs + off);
                ldsm4(al[mt][0], al[mt][1], al[mt][2], al[mt][3], Als + off);
            }
            #pragma unroll
            for (int p = 0; p < 2; p++) {
                uint32_t off = SWZ((uint32_t)((wn*32 + p*16 + b_row) * 128 + kk*32 + b_kb));
                ldsm4(bh[2*p][0], bh[2*p][1], bh[2*p+1][0], bh[2*p+1][1], Bhs + off);
                ldsm4(bl[2*p][0], bl[2*p][1], bl[2*p+1][0], bl[2*p+1][1], Bls + off);
            }
            #pragma unroll
            for (int mt = 0; mt < 4; mt++)
                #pragma unroll
                for (int nt = 0; nt < 4; nt++) {
                    mma_bf(acc[mt][nt], ah[mt], bh[nt]);
                    mma_bf(acc[mt][nt], ah[mt], bl[nt]);
                    mma_bf(acc[mt][nt], al[mt], bh[nt]);
                }
        }
        __syncthreads();
        int cn = c + 3;
        if (cn < nch) {
            uint32_t sd = sb + (cn % 3) * QSTAGEB;
            int k0 = cn * 64;
            load_tile(sd,           Ah, bm, Kd, k0, tid);
            load_tile(sd +   TILEB, Al, bm, Kd, k0, tid);
            load_tile(sd + 2*TILEB, Bh, bn, Kd, k0, tid);
            load_tile(sd + 3*TILEB, Bl, bn, Kd, k0, tid);
            CP_COMMIT();
        }
    }

    // epilogue: route to Q (scaled, bf16 pair), K (bf16 pair), V (fp16)
    int r0 = lane >> 2, c0 = (lane & 3) * 2;
    #pragma unroll
    for (int mt = 0; mt < 4; mt++) {
        #pragma unroll
        for (int nt = 0; nt < 4; nt++) {
            int col = bn + wn*32 + nt*8 + c0;
            float b0 = bias[col], b1 = bias[col + 1];
            int part = col >> 10;
            int head = (col >> 6) & 15;
            int d    = col & 63;
            #pragma unroll
            for (int half = 0; half < 2; half++) {
                int row = bm + wm*64 + mt*16 + r0 + half*8;
                float v0 = acc[mt][nt][half*2]     + b0;
                float v1 = acc[mt][nt][half*2 + 1] + b1;
                size_t off = ((((size_t)(row >> 11)) * 16 + head) * TT + (row & 2047)) * 64 + d;
                if (part == 2) {
                    *reinterpret_cast<__half2*>(Cv + off) =
                        __half2(__float2half(v0), __float2half(v1));
                } else {
                    if (part == 0) { v0 *= QSCALE; v1 *= QSCALE; }
                    __nv_bfloat16 h0, l0, h1, l1;
                    split2(v0, h0, l0); split2(v1, h1, l1);
                    __nv_bfloat16* Dh = (part == 0) ? Cqh : Ckh;
                    __nv_bfloat16* Dl = (part == 0) ? Cql : Ckl;
                    *reinterpret_cast<__nv_bfloat162*>(Dh + off) = __nv_bfloat162(h0, h1);
                    *reinterpret_cast<__nv_bfloat162*>(Dl + off) = __nv_bfloat162(l0, l1);
                }
            }
        }
    }
}

// ================= fp16 x2 GEMM (A pair, B single) =================
// EPI 1: fp32 + residual      EPI 2: gelu -> fp16 pair
#define FSTAGEB (3*TILEB)         // Ah, Al, B = 48KB
#define FGSMEM (2*FSTAGEB)        // 98304

template<int EPI>
__global__ void __launch_bounds__(256, 2) gemm_fp16x2(
    const __half* __restrict__ Ah, const __half* __restrict__ Al,
    const __half* __restrict__ B,
    const float* __restrict__ bias, const float* __restrict__ res,
    float* __restrict__ Cf, __half* __restrict__ Coh, __half* __restrict__ Col,
    int Nd, int Kd)
{
    extern __shared__ __align__(1024) char smem[];
    uint32_t sb = smem_u32(smem);
    int tid = threadIdx.x, wid = tid >> 5, lane = tid & 31;
    int wm = wid >> 2, wn = wid & 3;
    int bm = blockIdx.y * 128, bn = blockIdx.x * 128;

    float acc[4][4][4];
    #pragma unroll
    for (int mt = 0; mt < 4; mt++)
        #pragma unroll
        for (int nt = 0; nt < 4; nt++)
            #pragma unroll
            for (int r = 0; r < 4; r++) acc[mt][nt][r] = 0.f;

    int nch = Kd >> 6;

    #pragma unroll
    for (int s = 0; s < 2; s++) {
        uint32_t st = sb + s * FSTAGEB;
        int k0 = s * 64;
        load_tile(st,           Ah, bm, Kd, k0, tid);
        load_tile(st +   TILEB, Al, bm, Kd, k0, tid);
        load_tile(st + 2*TILEB, B,  bn, Kd, k0, tid);
        CP_COMMIT();
    }

    int grp = lane >> 3, rw = lane & 7;
    int a_row = (grp & 1) * 8 + rw;
    int a_kb  = (grp >> 1) * 16;
    int b_row = (grp >> 1) * 8 + rw;
    int b_kb  = (grp & 1) * 16;

    for (int c = 0; c < nch; c++) {
        if (c + 1 < nch) cpwait<1>(); else cpwait<0>();
        __syncthreads();
        uint32_t st = sb + (c & 1) * FSTAGEB;
        uint32_t Ahs = st, Als = st + TILEB, Bs = st + 2*TILEB;

        #pragma unroll
        for (int kk = 0; kk < 4; kk++) {
            uint32_t ah[4][4], al[4][4], bf[4][2];
            #pragma unroll
            for (int mt = 0; mt < 4; mt++) {
                uint32_t off = SWZ((uint32_t)((wm*64 + mt*16 + a_row) * 128 + kk*32 + a_kb));
                ldsm4(ah[mt][0], ah[mt][1], ah[mt][2], ah[mt][3], Ahs + off);
                ldsm4(al[mt][0], al[mt][1], al[mt][2], al[mt][3], Als + off);
            }
            #pragma unroll
            for (int p = 0; p < 2; p++) {
                uint32_t off = SWZ((uint32_t)((wn*32 + p*16 + b_row) * 128 + kk*32 + b_kb));
                ldsm4(bf[2*p][0], bf[2*p][1], bf[2*p+1][0], bf[2*p+1][1], Bs + off);
            }
            #pragma unroll
            for (int mt = 0; mt < 4; mt++)
                #pragma unroll
                for (int nt = 0; nt < 4; nt++) {
                    mma_fp(acc[mt][nt], ah[mt], bf[nt]);
                    mma_fp(acc[mt][nt], al[mt], bf[nt]);
                }
        }
        __syncthreads();
        int cn = c + 2;
        if (cn < nch) {
            int k0 = cn * 64;
            load_tile(st,           Ah, bm, Kd, k0, tid);
            load_tile(st +   TILEB, Al, bm, Kd, k0, tid);
            load_tile(st + 2*TILEB, B,  bn, Kd, k0, tid);
            CP_COMMIT();
        }
    }

    int r0 = lane >> 2, c0 = (lane & 3) * 2;
    #pragma unroll
    for (int mt = 0; mt < 4; mt++) {
        #pragma unroll
        for (int nt = 0; nt < 4; nt++) {
            int col = bn + wn*32 + nt*8 + c0;
            float b0 = bias[col], b1 = bias[col + 1];
            #pragma unroll
            for (int half = 0; half < 2; half++) {
                int row = bm + wm*64 + mt*16 + r0 + half*8;
                float v0 = acc[mt][nt][half*2]     + b0;
                float v1 = acc[mt][nt][half*2 + 1] + b1;
                size_t off = (size_t)row * Nd + col;
                if (EPI == 2) {
                    v0 = v0 * normcdff(v0);
                    v1 = v1 * normcdff(v1);
                    __half h0, l0, h1, l1;
                    split2h(v0, h0, l0); split2h(v1, h1, l1);
                    *reinterpret_cast<__half2*>(Coh + off) = __half2(h0, h1);
                    *reinterpret_cast<__half2*>(Col + off) = __half2(l0, l1);
                } else {
                    v0 += res[off]; v1 += res[off + 1];
                    *reinterpret_cast<float2*>(Cf + off) = make_float2(v0, v1);
                }
            }
        }
    }
}

// ================= flash attention: QK bf16x3, PV fp16x2 =================
// stage: Kh 8K | Kl 8K | V(fp16) 8K = 24KB; Q pair 32KB
#define ATSTG 24576
#define AT_SMEM (32768 + 2*ATSTG)   // 81920

__device__ __forceinline__ void load_kv(uint32_t st,
        const __nv_bfloat16* khp, const __nv_bfloat16* klp,
        const __half* vp, int kt, int tid) {
    int k0 = kt * 64;
    #pragma unroll
    for (int i = 0; i < 2; i++) {
        int idx = tid * 2 + i;
        int r = idx >> 3, gc = idx & 7;
        uint32_t off = SWZ((uint32_t)(r * 128 + gc * 16));
        size_t g = (size_t)(k0 + r) * 64 + gc * 8;
        cp16(st + off,         khp + g);
        cp16(st + 8192 + off,  klp + g);
        cp16(st + 16384 + off, vp + g);
    }
}

__global__ void __launch_bounds__(256, 1) attn_hmma(
    const __nv_bfloat16* __restrict__ Qh, const __nv_bfloat16* __restrict__ Ql,
    const __nv_bfloat16* __restrict__ Kh, const __nv_bfloat16* __restrict__ Kl,
    const __half* __restrict__ V,
    float* __restrict__ y)
{
    extern __shared__ __align__(1024) char smem[];
    uint32_t sb = smem_u32(smem);
    int tid = threadIdx.x, wid = tid >> 5, lane = tid & 31;
    int bhx = blockIdx.y, b = bhx >> 4, h = bhx & 15;
    int q0 = blockIdx.x * 128;
    size_t hb = (size_t)bhx * TT * DH;
    const __nv_bfloat16 *qhp = Qh + hb, *qlp = Ql + hb;
    const __nv_bfloat16 *khp = Kh + hb, *klp = Kl + hb;
    const __half *vp = V + hb;

    uint32_t sQh = sb, sQl = sb + 16384;
    uint32_t stg0 = sb + 32768, stg1 = sb + 32768 + ATSTG;

    int ntiles = 2 * (blockIdx.x + 1);

    load_tile(sQh, qhp, q0, 64, 0, tid);
    load_tile(sQl, qlp, q0, 64, 0, tid);
    load_kv(stg0, khp, klp, vp, 0, tid);
    CP_COMMIT();
    if (ntiles > 1) { load_kv(stg1, khp, klp, vp, 1, tid); CP_COMMIT(); }
    if (ntiles > 1) cpwait<1>(); else cpwait<0>();
    __syncthreads();

    int grp = lane >> 3, rw = lane & 7;
    int a_row = (grp & 1) * 8 + rw, a_kb = (grp >> 1) * 16;
    int b_row = (grp >> 1) * 8 + rw, b_kb = (grp & 1) * 16;
    int v_row = (grp & 1) * 8 + rw,  v_db = (grp >> 1) * 16;

    uint32_t qfh[4][4], qfl[4][4];
    #pragma unroll
    for (int kk = 0; kk < 4; kk++) {
        uint32_t off = SWZ((uint32_t)((wid*16 + a_row) * 128 + kk*32 + a_kb));
        ldsm4(qfh[kk][0], qfh[kk][1], qfh[kk][2], qfh[kk][3], sQh + off);
        ldsm4(qfl[kk][0], qfl[kk][1], qfl[kk][2], qfl[kk][3], sQl + off);
    }

    float o[8][4];
    #pragma unroll
    for (int nt = 0; nt < 8; nt++)
        #pragma unroll
        for (int r = 0; r < 4; r++) o[nt][r] = 0.f;
    float m0 = -1e30f, m1 = -1e30f, l0 = 0.f, l1 = 0.f;

    int qr0 = q0 + wid*16 + (lane >> 2);
    int kc0 = (lane & 3) * 2;

    for (int kt = 0; kt < ntiles; kt++) {
        if (kt > 0) {
            if (kt + 1 < ntiles) cpwait<1>(); else cpwait<0>();
            __syncthreads();
        }
        uint32_t st = (kt & 1) ? stg1 : stg0;
        int k0 = kt * 64;
        if (k0 <= q0 + wid*16 + 15) {
            uint32_t sKh = st, sKl = st + 8192, sV = st + 16384;
            float s[8][4];
            #pragma unroll
            for (int nt = 0; nt < 8; nt++)
                #pragma unroll
                for (int r = 0; r < 4; r++) s[nt][r] = 0.f;

            #pragma unroll
            for (int kk = 0; kk < 4; kk++) {
                uint32_t bhf[8][2], blf[8][2];
                #pragma unroll
                for (int p = 0; p < 4; p++) {
                    uint32_t off = SWZ((uint32_t)((p*16 + b_row) * 128 + kk*32 + b_kb));
                    ldsm4(bhf[2*p][0], bhf[2*p][1], bhf[2*p+1][0], bhf[2*p+1][1], sKh + off);
                    ldsm4(blf[2*p][0], blf[2*p][1], blf[2*p+1][0], blf[2*p+1][1], sKl + off);
                }
                #pragma unroll
                for (int nt = 0; nt < 8; nt++) {
                    mma_bf(s[nt], qfh[kk], bhf[nt]);
                    mma_bf(s[nt], qfh[kk], blf[nt]);
                    mma_bf(s[nt], qfl[kk], bhf[nt]);
                }
            }

            if (k0 + 63 > qr0) {
                #pragma unroll
                for (int nt = 0; nt < 8; nt++) {
                    int kg = k0 + nt*8 + kc0;
                    if (kg     > qr0)     s[nt][0] = -1e30f;
                    if (kg + 1 > qr0)     s[nt][1] = -1e30f;
                    if (kg     > qr0 + 8) s[nt][2] = -1e30f;
                    if (kg + 1 > qr0 + 8) s[nt][3] = -1e30f;
                }
            }

            float t0 = -1e30f, t1 = -1e30f;
            #pragma unroll
            for (int nt = 0; nt < 8; nt++) {
                t0 = fmaxf(t0, fmaxf(s[nt][0], s[nt][1]));
                t1 = fmaxf(t1, fmaxf(s[nt][2], s[nt][3]));
            }
            t0 = fmaxf(t0, __shfl_xor_sync(0xffffffffu, t0, 1));
            t0 = fmaxf(t0, __shfl_xor_sync(0xffffffffu, t0, 2));
            t1 = fmaxf(t1, __shfl_xor_sync(0xffffffffu, t1, 1));
            t1 = fmaxf(t1, __shfl_xor_sync(0xffffffffu, t1, 2));
            float mn0 = fmaxf(m0, t0), mn1 = fmaxf(m1, t1);
            float al0 = ex2f(m0 - mn0), al1 = ex2f(m1 - mn1);
            m0 = mn0; m1 = mn1;

            float ps0 = 0.f, ps1 = 0.f;
            uint32_t pah[4][4], pal[4][4];
            #pragma unroll
            for (int nt = 0; nt < 8; nt++) {
                float p0 = ex2f(s[nt][0] - m0), p1 = ex2f(s[nt][1] - m0);
                float p2 = ex2f(s[nt][2] - m1), p3 = ex2f(s[nt][3] - m1);
                ps0 += p0 + p1; ps1 += p2 + p3;
                __half h0,g0,h1,g1,h2,g2,h3,g3;
                split2h(p0,h0,g0); split2h(p1,h1,g1); split2h(p2,h2,g2); split2h(p3,h3,g3);
                int jj = nt >> 1, rb = (nt & 1) * 2;
                pah[jj][rb]   = pack2h(h0, h1);
                pah[jj][rb+1] = pack2h(h2, h3);
                pal[jj][rb]   = pack2h(g0, g1);
                pal[jj][rb+1] = pack2h(g2, g3);
            }
            ps0 += __shfl_xor_sync(0xffffffffu, ps0, 1);
            ps0 += __shfl_xor_sync(0xffffffffu, ps0, 2);
            ps1 += __shfl_xor_sync(0xffffffffu, ps1, 1);
            ps1 += __shfl_xor_sync(0xffffffffu, ps1, 2);
            l0 = al0 * l0 + ps0;
            l1 = al1 * l1 + ps1;
            #pragma unroll
            for (int nt = 0; nt < 8; nt++) {
                o[nt][0] *= al0; o[nt][1] *= al0;
                o[nt][2] *= al1; o[nt][3] *= al1;
            }

            #pragma unroll
            for (int j = 0; j < 4; j++) {
                uint32_t vf[8][2];
                #pragma unroll
                for (int p = 0; p < 4; p++) {
                    uint32_t off = SWZ((uint32_t)((j*16 + v_row) * 128 + p*32 + v_db));
                    ldsm4t(vf[2*p][0], vf[2*p][1], vf[2*p+1][0], vf[2*p+1][1], sV + off);
                }
                #pragma unroll
                for (int nt = 0; nt < 8; nt++) {
                    mma_fp(o[nt], pah[j], vf[nt]);
                    mma_fp(o[nt], pal[j], vf[nt]);
                }
            }
        }
        __syncthreads();
        if (kt + 2 < ntiles) {
            load_kv((kt & 1) ? stg1 : stg0, khp, klp, vp, kt + 2, tid);
            CP_COMMIT();
        }
    }

    float rl0 = 1.f / l0, rl1 = 1.f / l1;
    size_t base0 = ((size_t)(b*TT + qr0) * CC) + h*64 + kc0;
    size_t base1 = base0 + (size_t)8 * CC;
    #pragma unroll
    for (int nt = 0; nt < 8; nt++) {
        *reinterpret_cast<float2*>(y + base0 + nt*8) = make_float2(o[nt][0]*rl0, o[nt][1]*rl0);
        *reinterpret_cast<float2*>(y + base1 + nt*8) = make_float2(o[nt][2]*rl1, o[nt][3]*rl1);
    }
}

// ================= launch =================
extern "C" void kernel_launch(void* const* d_in, const int* in_sizes, int n_in,
                              void* d_out, int out_size) {
    const float* x       = (const float*)d_in[0];
    const float* ln1_w   = (const float*)d_in[1];
    const float* ln1_b   = (const float*)d_in[2];
    const float* W_attn  = (const float*)d_in[3];
    const float* b_attn  = (const float*)d_in[4];
    const float* W_aproj = (const float*)d_in[5];
    const float* b_aproj = (const float*)d_in[6];
    const float* ln2_w   = (const float*)d_in[7];
    const float* ln2_b   = (const float*)d_in[8];
    const float* W_fc    = (const float*)d_in[9];
    const float* b_fc    = (const float*)d_in[10];
    const float* W_mproj = (const float*)d_in[11];
    const float* b_mproj = (const float*)d_in[12];
    float* out = (float*)d_out;

    float *xn, *y, *x1;
    __nv_bfloat16 *xth, *xtl, *qh, *ql, *kh, *kl, *wah, *wal;
    __half *v, *yh, *yl, *hh, *hl, *fch, *fcl, *wap, *wfc, *wmp;
    cudaGetSymbolAddress((void**)&xn,  g_xn);
    cudaGetSymbolAddress((void**)&y,   g_y);
    cudaGetSymbolAddress((void**)&x1,  g_x1);
    cudaGetSymbolAddress((void**)&xth, g_xt_h); cudaGetSymbolAddress((void**)&xtl, g_xt_l);
    cudaGetSymbolAddress((void**)&yh,  g_yh);   cudaGetSymbolAddress((void**)&yl,  g_yl);
    cudaGetSymbolAddress((void**)&hh,  g_hh);   cudaGetSymbolAddress((void**)&hl,  g_hl);
    cudaGetSymbolAddress((void**)&fch, g_fch);  cudaGetSymbolAddress((void**)&fcl, g_fcl);
    cudaGetSymbolAddress((void**)&qh, g_qh); cudaGetSymbolAddress((void**)&ql, g_ql);
    cudaGetSymbolAddress((void**)&kh, g_kh); cudaGetSymbolAddress((void**)&kl, g_kl);
    cudaGetSymbolAddress((void**)&v,  g_v);
    cudaGetSymbolAddress((void**)&wah, g_wattn_h); cudaGetSymbolAddress((void**)&wal, g_wattn_l);
    cudaGetSymbolAddress((void**)&wap, g_waproj);
    cudaGetSymbolAddress((void**)&wfc, g_wfc);
    cudaGetSymbolAddress((void**)&wmp, g_wmproj);

    cudaFuncSetAttribute(attn_hmma, cudaFuncAttributeMaxDynamicSharedMemorySize, AT_SMEM);
    cudaFuncSetAttribute(gemm_qkv, cudaFuncAttributeMaxDynamicSharedMemorySize, QGSMEM);
    cudaFuncSetAttribute(gemm_fp16x2<1>, cudaFuncAttributeMaxDynamicSharedMemorySize, FGSMEM);
    cudaFuncSetAttribute(gemm_fp16x2<2>, cudaFuncAttributeMaxDynamicSharedMemorySize, FGSMEM);

    dim3 tb(32, 8);
    wsplit_kernel <<<dim3(3*CC/32, CC/32), tb>>>(W_attn,  wah, wal, CC, 3*CC);
    wtrans_h_kernel<<<dim3(CC/32,   CC/32), tb>>>(W_aproj, wap, CC,   CC);
    wtrans_h_kernel<<<dim3(4*CC/32, CC/32), tb>>>(W_fc,    wfc, CC,   4*CC);
    wtrans_h_kernel<<<dim3(CC/32, 4*CC/32), tb>>>(W_mproj, wmp, 4*CC, CC);

    // 1. LN1
    ln_kernel<<<NROWS, 256>>>(x, ln1_w, ln1_b, xn);
    // 2. logmap -> bf16 pair
    logmap_kernel<<<NROWS, 256>>>(xn, xth, xtl);
    // 3. QKV GEMM (bf16x3) -> Q/K pairs + V fp16
    gemm_qkv<<<dim3(3*CC/128, NROWS/128), 256, QGSMEM>>>(
        xth, xtl, wah, wal, b_attn, qh, ql, kh, kl, v);
    // 4. attention
    attn_hmma<<<dim3(TT/128, BB*HH), 256, AT_SMEM>>>(qh, ql, kh, kl, v, y);
    // 5. expmap -> fp16 pair
    expmap_kernel<<<NROWS, 256>>>(xn, y, yh, yl);
    // 6. aproj + residual -> x1 fp32 (fp16 x2)
    gemm_fp16x2<1><<<dim3(CC/128, NROWS/128), 256, FGSMEM>>>(
        yh, yl, wap, b_aproj, x, x1, nullptr, nullptr, CC, CC);
    // 7. LN2 -> fp16 pair
    ln_pair_kernel<<<NROWS, 256>>>(x1, ln2_w, ln2_b, hh, hl);
    // 8. FC + GELU -> fp16 pair (fp16 x2)
    gemm_fp16x2<2><<<dim3(4*CC/128, NROWS/128), 256, FGSMEM>>>(
        hh, hl, wfc, b_fc, nullptr, nullptr, fch, fcl, 4*CC, CC);
    // 9. mproj + residual -> out (fp16 x2)
    gemm_fp16x2<1><<<dim3(CC/128, NROWS/128), 256, FGSMEM>>>(
        fch, fcl, wmp, b_mproj, x1, out, nullptr, nullptr, CC, 4*CC);
}

// round 6
// speedup vs baseline: 4.1709x; 1.2933x over previous
#include <cuda_runtime.h>
#include <cuda_bf16.h>
#include <cuda_fp16.h>
#include <math.h>
#include <stdint.h>

#define BB 2
#define TT 2048
#define CC 1024
#define HH 16
#define DH 64
#define NROWS (BB*TT)          // 4096

// ================= static scratch =================
__device__ float g_xn [NROWS*CC];
__device__ float g_y  [NROWS*CC];
__device__ float g_x1 [NROWS*CC];

__device__ __nv_bfloat16 g_xt_h[NROWS*CC], g_xt_l[NROWS*CC];
__device__ __half        g_yh [NROWS*CC];
__device__ __half        g_hh [NROWS*CC];
__device__ __half        g_fch[NROWS*4*CC];

// attention Q/K bf16 hi/lo, V fp16 single, all [B,H,T,D]
__device__ __nv_bfloat16 g_qh[NROWS*CC], g_ql[NROWS*CC];
__device__ __nv_bfloat16 g_kh[NROWS*CC], g_kl[NROWS*CC];
__device__ __half        g_v [NROWS*CC];

// weights: qkv bf16 pair [N,K]; others fp16 single [N,K]
__device__ __nv_bfloat16 g_wattn_h[3*CC*CC], g_wattn_l[3*CC*CC];
__device__ __half g_waproj[CC*CC];
__device__ __half g_wfc   [4*CC*CC];
__device__ __half g_wmproj[CC*4*CC];

#define QSCALE 0.18033688011112042f   // 0.125 * log2(e)

// ================= helpers =================
__device__ __forceinline__ uint32_t smem_u32(const void* p) {
    uint32_t a;
    asm("{ .reg .u64 t; cvta.to.shared.u64 t, %1; cvt.u32.u64 %0, t; }" : "=r"(a) : "l"(p));
    return a;
}
#define SWZ(x) ((x) ^ (((x) >> 3) & 0x70))

__device__ __forceinline__ void cp16(uint32_t sa, const void* g) {
    asm volatile("cp.async.cg.shared.global [%0], [%1], 16;" :: "r"(sa), "l"(g));
}
#define CP_COMMIT() asm volatile("cp.async.commit_group;" ::: "memory")
template <int N> __device__ __forceinline__ void cpwait() {
    asm volatile("cp.async.wait_group %0;" :: "n"(N) : "memory");
}

__device__ __forceinline__ void ldsm4(uint32_t& r0, uint32_t& r1, uint32_t& r2, uint32_t& r3, uint32_t a) {
    asm volatile("ldmatrix.sync.aligned.m8n8.x4.shared.b16 {%0,%1,%2,%3}, [%4];"
        : "=r"(r0), "=r"(r1), "=r"(r2), "=r"(r3) : "r"(a));
}
__device__ __forceinline__ void ldsm4t(uint32_t& r0, uint32_t& r1, uint32_t& r2, uint32_t& r3, uint32_t a) {
    asm volatile("ldmatrix.sync.aligned.m8n8.x4.trans.shared.b16 {%0,%1,%2,%3}, [%4];"
        : "=r"(r0), "=r"(r1), "=r"(r2), "=r"(r3) : "r"(a));
}
__device__ __forceinline__ void mma_bf(float* c, const uint32_t* a, const uint32_t* b) {
    asm volatile("mma.sync.aligned.m16n8k16.row.col.f32.bf16.bf16.f32 "
        "{%0,%1,%2,%3}, {%4,%5,%6,%7}, {%8,%9}, {%0,%1,%2,%3};"
        : "+f"(c[0]), "+f"(c[1]), "+f"(c[2]), "+f"(c[3])
        : "r"(a[0]), "r"(a[1]), "r"(a[2]), "r"(a[3]), "r"(b[0]), "r"(b[1]));
}
__device__ __forceinline__ void mma_fp(float* c, const uint32_t* a, const uint32_t* b) {
    asm volatile("mma.sync.aligned.m16n8k16.row.col.f32.f16.f16.f32 "
        "{%0,%1,%2,%3}, {%4,%5,%6,%7}, {%8,%9}, {%0,%1,%2,%3};"
        : "+f"(c[0]), "+f"(c[1]), "+f"(c[2]), "+f"(c[3])
        : "r"(a[0]), "r"(a[1]), "r"(a[2]), "r"(a[3]), "r"(b[0]), "r"(b[1]));
}
__device__ __forceinline__ float ex2f(float x) {
    float r; asm("ex2.approx.f32 %0, %1;" : "=f"(r) : "f"(x)); return r;
}
__device__ __forceinline__ void split2(float v, __nv_bfloat16& h, __nv_bfloat16& l) {
    h = __float2bfloat16(v);
    l = __float2bfloat16(v - __bfloat162float(h));
}
__device__ __forceinline__ uint32_t pack2h(__half a, __half b) {
    __half2 t(a, b); return *reinterpret_cast<uint32_t*>(&t);
}

// ================= block reduce (256 thr) =================
__device__ __forceinline__ void block_reduce(float* vals, int n, float* scr) {
    int tid = threadIdx.x, lane = tid & 31, wid = tid >> 5;
    for (int k = 0; k < n; k++) {
        float v = vals[k];
        #pragma unroll
        for (int o = 16; o; o >>= 1) v += __shfl_xor_sync(0xffffffffu, v, o);
        if (lane == 0) scr[k*8 + wid] = v;
    }
    __syncthreads();
    if (tid == 0) {
        for (int k = 0; k < n; k++) {
            float s = 0.f;
            #pragma unroll
            for (int w = 0; w < 8; w++) s += scr[k*8 + w];
            scr[24 + k] = s;
        }
    }
    __syncthreads();
    for (int k = 0; k < n; k++) vals[k] = scr[24 + k];
    __syncthreads();
}

// ================= LayerNorm (fp32 out) =================
__global__ void ln_kernel(const float* __restrict__ x, const float* __restrict__ w,
                          const float* __restrict__ b, float* __restrict__ out) {
    __shared__ float scr[32];
    int row = blockIdx.x;
    const float* xr = x + (size_t)row * CC;
    float* orow = out + (size_t)row * CC;
    int tid = threadIdx.x;
    float v2[2] = {0.f, 0.f};
    for (int i = tid; i < CC; i += 256) { float v = xr[i]; v2[0] += v; v2[1] += v*v; }
    block_reduce(v2, 2, scr);
    float mean = v2[0] * (1.0f/CC);
    float var  = v2[1] * (1.0f/CC) - mean*mean;
    float inv  = rsqrtf(var + 1e-5f);
    for (int i = tid; i < CC; i += 256)
        orow[i] = (xr[i] - mean) * inv * w[i] + b[i];
}

// ================= LayerNorm (fp16 out) =================
__global__ void ln_half_kernel(const float* __restrict__ x, const float* __restrict__ w,
                               const float* __restrict__ b, __half* __restrict__ o) {
    __shared__ float scr[32];
    int row = blockIdx.x;
    const float* xr = x + (size_t)row * CC;
    int tid = threadIdx.x;
    float v2[2] = {0.f, 0.f};
    for (int i = tid; i < CC; i += 256) { float v = xr[i]; v2[0] += v; v2[1] += v*v; }
    block_reduce(v2, 2, scr);
    float mean = v2[0] * (1.0f/CC);
    float var  = v2[1] * (1.0f/CC) - mean*mean;
    float inv  = rsqrtf(var + 1e-5f);
    size_t base = (size_t)row * CC;
    for (int i = tid; i < CC; i += 256)
        o[base + i] = __float2half((xr[i] - mean) * inv * w[i] + b[i]);
}

// ================= logmap -> bf16 pair =================
__global__ void logmap_kernel(const float* __restrict__ xn,
                              __nv_bfloat16* __restrict__ oh, __nv_bfloat16* __restrict__ ol) {
    __shared__ float scr[32];
    __shared__ float ms[CC];
    int row = blockIdx.x;
    int t = row & (TT - 1);
    const float* u = xn + (size_t)row * CC;
    const float* a = (t == 0) ? nullptr : xn + (size_t)(row - 1) * CC;
    int tid = threadIdx.x;

    float v3[3] = {0.f, 0.f, 0.f};
    for (int i = tid; i < CC; i += 256) {
        float ui = u[i];
        float ai = a ? a[i] : 0.f;
        v3[0] += ai*ai; v3[1] += ui*ui; v3[2] += ai*ui;
    }
    block_reduce(v3, 3, scr);
    float an2 = v3[0], un2 = v3[1], ipau = v3[2];

    float coefX = 1.f - 2.f*ipau + un2;
    float coefU = 1.f - an2;
    float den   = 1.f - 2.f*ipau + an2*un2;
    float rden  = 1.f / den;

    float mn2v[1] = {0.f};
    for (int i = tid; i < CC; i += 256) {
        float ai = a ? a[i] : 0.f;
        float mi = (coefU * u[i] - coefX * ai) * rden;
        ms[i] = mi;
        mn2v[0] += mi*mi;
    }
    block_reduce(mn2v, 1, scr);
    float mn = sqrtf(mn2v[0]);
    float cf = 1.f + an2;
    float arg = fminf(sqrtf(mn), 0.999f);
    float scale = cf * atanhf(arg) / mn;
    size_t base = (size_t)row * CC;
    for (int i = tid; i < CC; i += 256) {
        __nv_bfloat16 h, l; split2(scale * ms[i], h, l);
        oh[base + i] = h; ol[base + i] = l;
    }
}

// ================= expmap: y fp32 -> fp16 =================
__global__ void expmap_kernel(const float* __restrict__ xn, const float* __restrict__ y,
                              __half* __restrict__ o) {
    __shared__ float scr[32];
    int row = blockIdx.x;
    int t = row & (TT - 1);
    const float* xr = (t == 0) ? nullptr : xn + (size_t)(row - 1) * CC;
    const float* v = y + (size_t)row * CC;
    int tid = threadIdx.x;

    float v3[3] = {0.f, 0.f, 0.f};
    for (int i = tid; i < CC; i += 256) {
        float vi = v[i];
        float xi = xr ? xr[i] : 0.f;
        v3[0] += xi*xi; v3[1] += vi*vi; v3[2] += xi*vi;
    }
    block_reduce(v3, 3, scr);
    float refn2 = v3[0], vn2 = v3[1], xv = v3[2];

    float lam = 2.f / (1.f + refn2);
    float vn  = sqrtf(vn2);
    float th  = tanhf(sqrtf(lam * vn2 * 0.5f));
    float ss  = th / vn;
    float secn2 = th * th;
    float ipxs  = ss * xv;
    float coefX = 1.f + 2.f*ipxs + secn2;
    float coefY = (1.f - refn2) * ss;
    float rden  = 1.f / (1.f + 2.f*ipxs + refn2*secn2);
    size_t base = (size_t)row * CC;
    for (int i = tid; i < CC; i += 256) {
        float xi = xr ? xr[i] : 0.f;
        o[base + i] = __float2half((coefX * xi + coefY * v[i]) * rden);
    }
}

// ================= weight transpose kernels =================
__global__ void wsplit_kernel(const float* __restrict__ W,
                              __nv_bfloat16* __restrict__ Wh, __nv_bfloat16* __restrict__ Wl,
                              int K, int N) {
    __shared__ float t[32][33];
    int n0 = blockIdx.x * 32, k0 = blockIdx.y * 32;
    int tx = threadIdx.x, ty = threadIdx.y;
    #pragma unroll
    for (int j = 0; j < 32; j += 8)
        t[ty + j][tx] = W[(size_t)(k0 + ty + j) * N + n0 + tx];
    __syncthreads();
    #pragma unroll
    for (int j = 0; j < 32; j += 8) {
        float v = t[tx][ty + j];
        __nv_bfloat16 h, l; split2(v, h, l);
        size_t o = (size_t)(n0 + ty + j) * K + k0 + tx;
        Wh[o] = h; Wl[o] = l;
    }
}

__global__ void wtrans_h_kernel(const float* __restrict__ W, __half* __restrict__ Wt,
                                int K, int N) {
    __shared__ float t[32][33];
    int n0 = blockIdx.x * 32, k0 = blockIdx.y * 32;
    int tx = threadIdx.x, ty = threadIdx.y;
    #pragma unroll
    for (int j = 0; j < 32; j += 8)
        t[ty + j][tx] = W[(size_t)(k0 + ty + j) * N + n0 + tx];
    __syncthreads();
    #pragma unroll
    for (int j = 0; j < 32; j += 8)
        Wt[(size_t)(n0 + ty + j) * K + k0 + tx] = __float2half(t[tx][ty + j]);
}

// ================= shared tile loader =================
#define TILEB 16384
__device__ __forceinline__ void load_tile(uint32_t sdst, const void* gv,
                                          int row0, int Kd, int k0, int tid) {
    const __nv_bfloat16* base = (const __nv_bfloat16*)gv + (size_t)row0 * Kd + k0;
    #pragma unroll
    for (int i = 0; i < 4; i++) {
        int idx = tid * 4 + i;
        int r = idx >> 3, gc = idx & 7;
        uint32_t so = sdst + SWZ((uint32_t)(r * 128 + gc * 16));
        cp16(so, base + (size_t)r * Kd + gc * 8);
    }
}

// ================= QKV GEMM: bf16x3, 3-stage, epilogue -> Q/K pairs + V fp16 =================
#define QSTAGEB (4*TILEB)
#define QGSMEM (3*QSTAGEB)

__global__ void __launch_bounds__(256, 1) gemm_qkv(
    const __nv_bfloat16* __restrict__ Ah, const __nv_bfloat16* __restrict__ Al,
    const __nv_bfloat16* __restrict__ Bh, const __nv_bfloat16* __restrict__ Bl,
    const float* __restrict__ bias,
    __nv_bfloat16* __restrict__ Cqh, __nv_bfloat16* __restrict__ Cql,
    __nv_bfloat16* __restrict__ Ckh, __nv_bfloat16* __restrict__ Ckl,
    __half* __restrict__ Cv)
{
    const int Kd = CC;
    extern __shared__ __align__(1024) char smem[];
    uint32_t sb = smem_u32(smem);
    int tid = threadIdx.x, wid = tid >> 5, lane = tid & 31;
    int wm = wid >> 2, wn = wid & 3;
    int bm = blockIdx.y * 128, bn = blockIdx.x * 128;

    float acc[4][4][4];
    #pragma unroll
    for (int mt = 0; mt < 4; mt++)
        #pragma unroll
        for (int nt = 0; nt < 4; nt++)
            #pragma unroll
            for (int r = 0; r < 4; r++) acc[mt][nt][r] = 0.f;

    const int nch = Kd >> 6;

    #pragma unroll
    for (int s = 0; s < 3; s++) {
        uint32_t st = sb + s * QSTAGEB;
        int k0 = s * 64;
        load_tile(st,           Ah, bm, Kd, k0, tid);
        load_tile(st +   TILEB, Al, bm, Kd, k0, tid);
        load_tile(st + 2*TILEB, Bh, bn, Kd, k0, tid);
        load_tile(st + 3*TILEB, Bl, bn, Kd, k0, tid);
        CP_COMMIT();
    }

    int grp = lane >> 3, rw = lane & 7;
    int a_row = (grp & 1) * 8 + rw;
    int a_kb  = (grp >> 1) * 16;
    int b_row = (grp >> 1) * 8 + rw;
    int b_kb  = (grp & 1) * 16;

    for (int c = 0; c < nch; c++) {
        int rem = nch - 1 - c;
        if (rem >= 2) cpwait<2>(); else if (rem == 1) cpwait<1>(); else cpwait<0>();
        __syncthreads();
        uint32_t st = sb + (c % 3) * QSTAGEB;
        uint32_t Ahs = st, Als = st + TILEB, Bhs = st + 2*TILEB, Bls = st + 3*TILEB;

        #pragma unroll
        for (int kk = 0; kk < 4; kk++) {
            uint32_t ah[4][4], al[4][4], bh[4][2], bl[4][2];
            #pragma unroll
            for (int mt = 0; mt < 4; mt++) {
                uint32_t off = SWZ((uint32_t)((wm*64 + mt*16 + a_row) * 128 + kk*32 + a_kb));
                ldsm4(ah[mt][0], ah[mt][1], ah[mt][2], ah[mt][3], Ahs + off);
                ldsm4(al[mt][0], al[mt][1], al[mt][2], al[mt][3], Als + off);
            }
            #pragma unroll
            for (int p = 0; p < 2; p++) {
                uint32_t off = SWZ((uint32_t)((wn*32 + p*16 + b_row) * 128 + kk*32 + b_kb));
                ldsm4(bh[2*p][0], bh[2*p][1], bh[2*p+1][0], bh[2*p+1][1], Bhs + off);
                ldsm4(bl[2*p][0], bl[2*p][1], bl[2*p+1][0], bl[2*p+1][1], Bls + off);
            }
            #pragma unroll
            for (int mt = 0; mt < 4; mt++)
                #pragma unroll
                for (int nt = 0; nt < 4; nt++) {
                    mma_bf(acc[mt][nt], ah[mt], bh[nt]);
                    mma_bf(acc[mt][nt], ah[mt], bl[nt]);
                    mma_bf(acc[mt][nt], al[mt], bh[nt]);
                }
        }
        __syncthreads();
        int cn = c + 3;
        if (cn < nch) {
            uint32_t sd = sb + (cn % 3) * QSTAGEB;
            int k0 = cn * 64;
            load_tile(sd,           Ah, bm, Kd, k0, tid);
            load_tile(sd +   TILEB, Al, bm, Kd, k0, tid);
            load_tile(sd + 2*TILEB, Bh, bn, Kd, k0, tid);
            load_tile(sd + 3*TILEB, Bl, bn, Kd, k0, tid);
            CP_COMMIT();
        }
    }

    int r0 = lane >> 2, c0 = (lane & 3) * 2;
    #pragma unroll
    for (int mt = 0; mt < 4; mt++) {
        #pragma unroll
        for (int nt = 0; nt < 4; nt++) {
            int col = bn + wn*32 + nt*8 + c0;
            float b0 = bias[col], b1 = bias[col + 1];
            int part = col >> 10;
            int head = (col >> 6) & 15;
            int d    = col & 63;
            #pragma unroll
            for (int half = 0; half < 2; half++) {
                int row = bm + wm*64 + mt*16 + r0 + half*8;
                float v0 = acc[mt][nt][half*2]     + b0;
                float v1 = acc[mt][nt][half*2 + 1] + b1;
                size_t off = ((((size_t)(row >> 11)) * 16 + head) * TT + (row & 2047)) * 64 + d;
                if (part == 2) {
                    *reinterpret_cast<__half2*>(Cv + off) =
                        __half2(__float2half(v0), __float2half(v1));
                } else {
                    if (part == 0) { v0 *= QSCALE; v1 *= QSCALE; }
                    __nv_bfloat16 h0, l0, h1, l1;
                    split2(v0, h0, l0); split2(v1, h1, l1);
                    __nv_bfloat16* Dh = (part == 0) ? Cqh : Ckh;
                    __nv_bfloat16* Dl = (part == 0) ? Cql : Ckl;
                    *reinterpret_cast<__nv_bfloat162*>(Dh + off) = __nv_bfloat162(h0, h1);
                    *reinterpret_cast<__nv_bfloat162*>(Dl + off) = __nv_bfloat162(l0, l1);
                }
            }
        }
    }
}

// ================= fp16 x1 GEMM (A single, B single) =================
// EPI 1: fp32 + residual      EPI 2: gelu -> fp16
#define F1STAGE (2*TILEB)         // A, B = 32KB
#define F1SMEM (2*F1STAGE)        // 65536

template<int EPI>
__global__ void __launch_bounds__(256, 2) gemm_fp16(
    const __half* __restrict__ A, const __half* __restrict__ B,
    const float* __restrict__ bias, const float* __restrict__ res,
    float* __restrict__ Cf, __half* __restrict__ Co,
    int Nd, int Kd)
{
    extern __shared__ __align__(1024) char smem[];
    uint32_t sb = smem_u32(smem);
    int tid = threadIdx.x, wid = tid >> 5, lane = tid & 31;
    int wm = wid >> 2, wn = wid & 3;
    int bm = blockIdx.y * 128, bn = blockIdx.x * 128;

    float acc[4][4][4];
    #pragma unroll
    for (int mt = 0; mt < 4; mt++)
        #pragma unroll
        for (int nt = 0; nt < 4; nt++)
            #pragma unroll
            for (int r = 0; r < 4; r++) acc[mt][nt][r] = 0.f;

    int nch = Kd >> 6;

    #pragma unroll
    for (int s = 0; s < 2; s++) {
        uint32_t st = sb + s * F1STAGE;
        int k0 = s * 64;
        load_tile(st,         A, bm, Kd, k0, tid);
        load_tile(st + TILEB, B, bn, Kd, k0, tid);
        CP_COMMIT();
    }

    int grp = lane >> 3, rw = lane & 7;
    int a_row = (grp & 1) * 8 + rw;
    int a_kb  = (grp >> 1) * 16;
    int b_row = (grp >> 1) * 8 + rw;
    int b_kb  = (grp & 1) * 16;

    for (int c = 0; c < nch; c++) {
        if (c + 1 < nch) cpwait<1>(); else cpwait<0>();
        __syncthreads();
        uint32_t st = sb + (c & 1) * F1STAGE;
        uint32_t As = st, Bs = st + TILEB;

        #pragma unroll
        for (int kk = 0; kk < 4; kk++) {
            uint32_t af[4][4], bf[4][2];
            #pragma unroll
            for (int mt = 0; mt < 4; mt++) {
                uint32_t off = SWZ((uint32_t)((wm*64 + mt*16 + a_row) * 128 + kk*32 + a_kb));
                ldsm4(af[mt][0], af[mt][1], af[mt][2], af[mt][3], As + off);
            }
            #pragma unroll
            for (int p = 0; p < 2; p++) {
                uint32_t off = SWZ((uint32_t)((wn*32 + p*16 + b_row) * 128 + kk*32 + b_kb));
                ldsm4(bf[2*p][0], bf[2*p][1], bf[2*p+1][0], bf[2*p+1][1], Bs + off);
            }
            #pragma unroll
            for (int mt = 0; mt < 4; mt++)
                #pragma unroll
                for (int nt = 0; nt < 4; nt++)
                    mma_fp(acc[mt][nt], af[mt], bf[nt]);
        }
        __syncthreads();
        int cn = c + 2;
        if (cn < nch) {
            int k0 = cn * 64;
            load_tile(st,         A, bm, Kd, k0, tid);
            load_tile(st + TILEB, B, bn, Kd, k0, tid);
            CP_COMMIT();
        }
    }

    int r0 = lane >> 2, c0 = (lane & 3) * 2;
    #pragma unroll
    for (int mt = 0; mt < 4; mt++) {
        #pragma unroll
        for (int nt = 0; nt < 4; nt++) {
            int col = bn + wn*32 + nt*8 + c0;
            float b0 = bias[col], b1 = bias[col + 1];
            #pragma unroll
            for (int half = 0; half < 2; half++) {
                int row = bm + wm*64 + mt*16 + r0 + half*8;
                float v0 = acc[mt][nt][half*2]     + b0;
                float v1 = acc[mt][nt][half*2 + 1] + b1;
                size_t off = (size_t)row * Nd + col;
                if (EPI == 2) {
                    v0 = v0 * normcdff(v0);
                    v1 = v1 * normcdff(v1);
                    *reinterpret_cast<__half2*>(Co + off) =
                        __half2(__float2half(v0), __float2half(v1));
                } else {
                    v0 += res[off]; v1 += res[off + 1];
                    *reinterpret_cast<float2*>(Cf + off) = make_float2(v0, v1);
                }
            }
        }
    }
}

// ================= flash attention: QK bf16x3, PV fp16x1 =================
#define ATSTG 24576
#define AT_SMEM (32768 + 2*ATSTG)   // 81920

__device__ __forceinline__ void load_kv(uint32_t st,
        const __nv_bfloat16* khp, const __nv_bfloat16* klp,
        const __half* vp, int kt, int tid) {
    int k0 = kt * 64;
    #pragma unroll
    for (int i = 0; i < 2; i++) {
        int idx = tid * 2 + i;
        int r = idx >> 3, gc = idx & 7;
        uint32_t off = SWZ((uint32_t)(r * 128 + gc * 16));
        size_t g = (size_t)(k0 + r) * 64 + gc * 8;
        cp16(st + off,         khp + g);
        cp16(st + 8192 + off,  klp + g);
        cp16(st + 16384 + off, vp + g);
    }
}

__global__ void __launch_bounds__(256, 1) attn_hmma(
    const __nv_bfloat16* __restrict__ Qh, const __nv_bfloat16* __restrict__ Ql,
    const __nv_bfloat16* __restrict__ Kh, const __nv_bfloat16* __restrict__ Kl,
    const __half* __restrict__ V,
    float* __restrict__ y)
{
    extern __shared__ __align__(1024) char smem[];
    uint32_t sb = smem_u32(smem);
    int tid = threadIdx.x, wid = tid >> 5, lane = tid & 31;
    int bhx = blockIdx.y, b = bhx >> 4, h = bhx & 15;
    int q0 = blockIdx.x * 128;
    size_t hb = (size_t)bhx * TT * DH;
    const __nv_bfloat16 *qhp = Qh + hb, *qlp = Ql + hb;
    const __nv_bfloat16 *khp = Kh + hb, *klp = Kl + hb;
    const __half *vp = V + hb;

    uint32_t sQh = sb, sQl = sb + 16384;
    uint32_t stg0 = sb + 32768, stg1 = sb + 32768 + ATSTG;

    int ntiles = 2 * (blockIdx.x + 1);

    load_tile(sQh, qhp, q0, 64, 0, tid);
    load_tile(sQl, qlp, q0, 64, 0, tid);
    load_kv(stg0, khp, klp, vp, 0, tid);
    CP_COMMIT();
    if (ntiles > 1) { load_kv(stg1, khp, klp, vp, 1, tid); CP_COMMIT(); }
    if (ntiles > 1) cpwait<1>(); else cpwait<0>();
    __syncthreads();

    int grp = lane >> 3, rw = lane & 7;
    int a_row = (grp & 1) * 8 + rw, a_kb = (grp >> 1) * 16;
    int b_row = (grp >> 1) * 8 + rw, b_kb = (grp & 1) * 16;
    int v_row = (grp & 1) * 8 + rw,  v_db = (grp >> 1) * 16;

    uint32_t qfh[4][4], qfl[4][4];
    #pragma unroll
    for (int kk = 0; kk < 4; kk++) {
        uint32_t off = SWZ((uint32_t)((wid*16 + a_row) * 128 + kk*32 + a_kb));
        ldsm4(qfh[kk][0], qfh[kk][1], qfh[kk][2], qfh[kk][3], sQh + off);
        ldsm4(qfl[kk][0], qfl[kk][1], qfl[kk][2], qfl[kk][3], sQl + off);
    }

    float o[8][4];
    #pragma unroll
    for (int nt = 0; nt < 8; nt++)
        #pragma unroll
        for (int r = 0; r < 4; r++) o[nt][r] = 0.f;
    float m0 = -1e30f, m1 = -1e30f, l0 = 0.f, l1 = 0.f;

    int qr0 = q0 + wid*16 + (lane >> 2);
    int kc0 = (lane & 3) * 2;

    for (int kt = 0; kt < ntiles; kt++) {
        if (kt > 0) {
            if (kt + 1 < ntiles) cpwait<1>(); else cpwait<0>();
            __syncthreads();
        }
        uint32_t st = (kt & 1) ? stg1 : stg0;
        int k0 = kt * 64;
        if (k0 <= q0 + wid*16 + 15) {
            uint32_t sKh = st, sKl = st + 8192, sV = st + 16384;
            float s[8][4];
            #pragma unroll
            for (int nt = 0; nt < 8; nt++)
                #pragma unroll
                for (int r = 0; r < 4; r++) s[nt][r] = 0.f;

            #pragma unroll
            for (int kk = 0; kk < 4; kk++) {
                uint32_t bhf[8][2], blf[8][2];
                #pragma unroll
                for (int p = 0; p < 4; p++) {
                    uint32_t off = SWZ((uint32_t)((p*16 + b_row) * 128 + kk*32 + b_kb));
                    ldsm4(bhf[2*p][0], bhf[2*p][1], bhf[2*p+1][0], bhf[2*p+1][1], sKh + off);
                    ldsm4(blf[2*p][0], blf[2*p][1], blf[2*p+1][0], blf[2*p+1][1], sKl + off);
                }
                #pragma unroll
                for (int nt = 0; nt < 8; nt++) {
                    mma_bf(s[nt], qfh[kk], bhf[nt]);
                    mma_bf(s[nt], qfh[kk], blf[nt]);
                    mma_bf(s[nt], qfl[kk], bhf[nt]);
                }
            }

            if (k0 + 63 > qr0) {
                #pragma unroll
                for (int nt = 0; nt < 8; nt++) {
                    int kg = k0 + nt*8 + kc0;
                    if (kg     > qr0)     s[nt][0] = -1e30f;
                    if (kg + 1 > qr0)     s[nt][1] = -1e30f;
                    if (kg     > qr0 + 8) s[nt][2] = -1e30f;
                    if (kg + 1 > qr0 + 8) s[nt][3] = -1e30f;
                }
            }

            float t0 = -1e30f, t1 = -1e30f;
            #pragma unroll
            for (int nt = 0; nt < 8; nt++) {
                t0 = fmaxf(t0, fmaxf(s[nt][0], s[nt][1]));
                t1 = fmaxf(t1, fmaxf(s[nt][2], s[nt][3]));
            }
            t0 = fmaxf(t0, __shfl_xor_sync(0xffffffffu, t0, 1));
            t0 = fmaxf(t0, __shfl_xor_sync(0xffffffffu, t0, 2));
            t1 = fmaxf(t1, __shfl_xor_sync(0xffffffffu, t1, 1));
            t1 = fmaxf(t1, __shfl_xor_sync(0xffffffffu, t1, 2));
            float mn0 = fmaxf(m0, t0), mn1 = fmaxf(m1, t1);
            float al0 = ex2f(m0 - mn0), al1 = ex2f(m1 - mn1);
            m0 = mn0; m1 = mn1;

            float ps0 = 0.f, ps1 = 0.f;
            uint32_t pa[4][4];
            #pragma unroll
            for (int nt = 0; nt < 8; nt++) {
                float p0 = ex2f(s[nt][0] - m0), p1 = ex2f(s[nt][1] - m0);
                float p2 = ex2f(s[nt][2] - m1), p3 = ex2f(s[nt][3] - m1);
                ps0 += p0 + p1; ps1 += p2 + p3;
                int jj = nt >> 1, rb = (nt & 1) * 2;
                pa[jj][rb]   = pack2h(__float2half(p0), __float2half(p1));
                pa[jj][rb+1] = pack2h(__float2half(p2), __float2half(p3));
            }
            ps0 += __shfl_xor_sync(0xffffffffu, ps0, 1);
            ps0 += __shfl_xor_sync(0xffffffffu, ps0, 2);
            ps1 += __shfl_xor_sync(0xffffffffu, ps1, 1);
            ps1 += __shfl_xor_sync(0xffffffffu, ps1, 2);
            l0 = al0 * l0 + ps0;
            l1 = al1 * l1 + ps1;
            #pragma unroll
            for (int nt = 0; nt < 8; nt++) {
                o[nt][0] *= al0; o[nt][1] *= al0;
                o[nt][2] *= al1; o[nt][3] *= al1;
            }

            #pragma unroll
            for (int j = 0; j < 4; j++) {
                uint32_t vf[8][2];
                #pragma unroll
                for (int p = 0; p < 4; p++) {
                    uint32_t off = SWZ((uint32_t)((j*16 + v_row) * 128 + p*32 + v_db));
                    ldsm4t(vf[2*p][0], vf[2*p][1], vf[2*p+1][0], vf[2*p+1][1], sV + off);
                }
                #pragma unroll
                for (int nt = 0; nt < 8; nt++)
                    mma_fp(o[nt], pa[j], vf[nt]);
            }
        }
        __syncthreads();
        if (kt + 2 < ntiles) {
            load_kv((kt & 1) ? stg1 : stg0, khp, klp, vp, kt + 2, tid);
            CP_COMMIT();
        }
    }

    float rl0 = 1.f / l0, rl1 = 1.f / l1;
    size_t base0 = ((size_t)(b*TT + qr0) * CC) + h*64 + kc0;
    size_t base1 = base0 + (size_t)8 * CC;
    #pragma unroll
    for (int nt = 0; nt < 8; nt++) {
        *reinterpret_cast<float2*>(y + base0 + nt*8) = make_float2(o[nt][0]*rl0, o[nt][1]*rl0);
        *reinterpret_cast<float2*>(y + base1 + nt*8) = make_float2(o[nt][2]*rl1, o[nt][3]*rl1);
    }
}

// ================= launch =================
extern "C" void kernel_launch(void* const* d_in, const int* in_sizes, int n_in,
                              void* d_out, int out_size) {
    const float* x       = (const float*)d_in[0];
    const float* ln1_w   = (const float*)d_in[1];
    const float* ln1_b   = (const float*)d_in[2];
    const float* W_attn  = (const float*)d_in[3];
    const float* b_attn  = (const float*)d_in[4];
    const float* W_aproj = (const float*)d_in[5];
    const float* b_aproj = (const float*)d_in[6];
    const float* ln2_w   = (const float*)d_in[7];
    const float* ln2_b   = (const float*)d_in[8];
    const float* W_fc    = (const float*)d_in[9];
    const float* b_fc    = (const float*)d_in[10];
    const float* W_mproj = (const float*)d_in[11];
    const float* b_mproj = (const float*)d_in[12];
    float* out = (float*)d_out;

    float *xn, *y, *x1;
    __nv_bfloat16 *xth, *xtl, *qh, *ql, *kh, *kl, *wah, *wal;
    __half *v, *yh, *hh, *fch, *wap, *wfc, *wmp;
    cudaGetSymbolAddress((void**)&xn,  g_xn);
    cudaGetSymbolAddress((void**)&y,   g_y);
    cudaGetSymbolAddress((void**)&x1,  g_x1);
    cudaGetSymbolAddress((void**)&xth, g_xt_h); cudaGetSymbolAddress((void**)&xtl, g_xt_l);
    cudaGetSymbolAddress((void**)&yh,  g_yh);
    cudaGetSymbolAddress((void**)&hh,  g_hh);
    cudaGetSymbolAddress((void**)&fch, g_fch);
    cudaGetSymbolAddress((void**)&qh, g_qh); cudaGetSymbolAddress((void**)&ql, g_ql);
    cudaGetSymbolAddress((void**)&kh, g_kh); cudaGetSymbolAddress((void**)&kl, g_kl);
    cudaGetSymbolAddress((void**)&v,  g_v);
    cudaGetSymbolAddress((void**)&wah, g_wattn_h); cudaGetSymbolAddress((void**)&wal, g_wattn_l);
    cudaGetSymbolAddress((void**)&wap, g_waproj);
    cudaGetSymbolAddress((void**)&wfc, g_wfc);
    cudaGetSymbolAddress((void**)&wmp, g_wmproj);

    cudaFuncSetAttribute(attn_hmma, cudaFuncAttributeMaxDynamicSharedMemorySize, AT_SMEM);
    cudaFuncSetAttribute(gemm_qkv, cudaFuncAttributeMaxDynamicSharedMemorySize, QGSMEM);
    cudaFuncSetAttribute(gemm_fp16<1>, cudaFuncAttributeMaxDynamicSharedMemorySize, F1SMEM);
    cudaFuncSetAttribute(gemm_fp16<2>, cudaFuncAttributeMaxDynamicSharedMemorySize, F1SMEM);

    dim3 tb(32, 8);
    wsplit_kernel  <<<dim3(3*CC/32, CC/32), tb>>>(W_attn,  wah, wal, CC, 3*CC);
    wtrans_h_kernel<<<dim3(CC/32,   CC/32), tb>>>(W_aproj, wap, CC,   CC);
    wtrans_h_kernel<<<dim3(4*CC/32, CC/32), tb>>>(W_fc,    wfc, CC,   4*CC);
    wtrans_h_kernel<<<dim3(CC/32, 4*CC/32), tb>>>(W_mproj, wmp, 4*CC, CC);

    // 1. LN1
    ln_kernel<<<NROWS, 256>>>(x, ln1_w, ln1_b, xn);
    // 2. logmap -> bf16 pair
    logmap_kernel<<<NROWS, 256>>>(xn, xth, xtl);
    // 3. QKV GEMM (bf16x3) -> Q/K pairs + V fp16
    gemm_qkv<<<dim3(3*CC/128, NROWS/128), 256, QGSMEM>>>(
        xth, xtl, wah, wal, b_attn, qh, ql, kh, kl, v);
    // 4. attention
    attn_hmma<<<dim3(TT/128, BB*HH), 256, AT_SMEM>>>(qh, ql, kh, kl, v, y);
    // 5. expmap -> fp16
    expmap_kernel<<<NROWS, 256>>>(xn, y, yh);
    // 6. aproj + residual -> x1 fp32 (fp16 x1)
    gemm_fp16<1><<<dim3(CC/128, NROWS/128), 256, F1SMEM>>>(
        yh, wap, b_aproj, x, x1, nullptr, CC, CC);
    // 7. LN2 -> fp16
    ln_half_kernel<<<NROWS, 256>>>(x1, ln2_w, ln2_b, hh);
    // 8. FC + GELU -> fp16 (fp16 x1)
    gemm_fp16<2><<<dim3(4*CC/128, NROWS/128), 256, F1SMEM>>>(
        hh, wfc, b_fc, nullptr, nullptr, fch, 4*CC, CC);
    // 9. mproj + residual -> out (fp16 x1)
    gemm_fp16<1><<<dim3(CC/128, NROWS/128), 256, F1SMEM>>>(
        fch, wmp, b_mproj, x1, out, nullptr, CC, 4*CC);
}

// round 8
// speedup vs baseline: 4.3647x; 1.0465x over previous
#include <cuda_runtime.h>
#include <cuda_fp16.h>
#include <math.h>
#include <stdint.h>

#define BB 2
#define TT 2048
#define CC 1024
#define HH 16
#define DH 64
#define NROWS (BB*TT)          // 4096

// ================= static scratch =================
__device__ float g_y  [NROWS*CC];
__device__ float g_x1 [NROWS*CC];

__device__ __half g_xt_h[NROWS*CC], g_xt_l[NROWS*CC];
__device__ __half g_yh [NROWS*CC];
__device__ __half g_hh [NROWS*CC];
__device__ __half g_fch[NROWS*4*CC];

// attention Q/K fp16 hi/lo, V fp16 single, all [B,H,T,D]
__device__ __half g_qh[NROWS*CC], g_ql[NROWS*CC];
__device__ __half g_kh[NROWS*CC], g_kl[NROWS*CC];
__device__ __half g_v [NROWS*CC];

// weights: qkv fp16 pair [N,K]; others fp16 single [N,K]
__device__ __half g_wattn_h[3*CC*CC], g_wattn_l[3*CC*CC];
__device__ __half g_waproj[CC*CC];
__device__ __half g_wfc   [4*CC*CC];
__device__ __half g_wmproj[CC*4*CC];

#define QSCALE 0.18033688011112042f   // 0.125 * log2(e)

// ================= helpers =================
__device__ __forceinline__ uint32_t smem_u32(const void* p) {
    uint32_t a;
    asm("{ .reg .u64 t; cvta.to.shared.u64 t, %1; cvt.u32.u64 %0, t; }" : "=r"(a) : "l"(p));
    return a;
}
#define SWZ(x) ((x) ^ (((x) >> 3) & 0x70))

__device__ __forceinline__ void cp16(uint32_t sa, const void* g) {
    asm volatile("cp.async.cg.shared.global [%0], [%1], 16;" :: "r"(sa), "l"(g));
}
#define CP_COMMIT() asm volatile("cp.async.commit_group;" ::: "memory")
template <int N> __device__ __forceinline__ void cpwait() {
    asm volatile("cp.async.wait_group %0;" :: "n"(N) : "memory");
}

__device__ __forceinline__ void ldsm4(uint32_t& r0, uint32_t& r1, uint32_t& r2, uint32_t& r3, uint32_t a) {
    asm volatile("ldmatrix.sync.aligned.m8n8.x4.shared.b16 {%0,%1,%2,%3}, [%4];"
        : "=r"(r0), "=r"(r1), "=r"(r2), "=r"(r3) : "r"(a));
}
__device__ __forceinline__ void ldsm4t(uint32_t& r0, uint32_t& r1, uint32_t& r2, uint32_t& r3, uint32_t a) {
    asm volatile("ldmatrix.sync.aligned.m8n8.x4.trans.shared.b16 {%0,%1,%2,%3}, [%4];"
        : "=r"(r0), "=r"(r1), "=r"(r2), "=r"(r3) : "r"(a));
}
__device__ __forceinline__ void mma_fp(float* c, const uint32_t* a, const uint32_t* b) {
    asm volatile("mma.sync.aligned.m16n8k16.row.col.f32.f16.f16.f32 "
        "{%0,%1,%2,%3}, {%4,%5,%6,%7}, {%8,%9}, {%0,%1,%2,%3};"
        : "+f"(c[0]), "+f"(c[1]), "+f"(c[2]), "+f"(c[3])
        : "r"(a[0]), "r"(a[1]), "r"(a[2]), "r"(a[3]), "r"(b[0]), "r"(b[1]));
}
__device__ __forceinline__ float ex2f(float x) {
    float r; asm("ex2.approx.f32 %0, %1;" : "=f"(r) : "f"(x)); return r;
}
__device__ __forceinline__ void split2h(float v, __half& h, __half& l) {
    h = __float2half(v);
    l = __float2half(v - __half2float(h));
}
__device__ __forceinline__ uint32_t pack2h(__half a, __half b) {
    __half2 t(a, b); return *reinterpret_cast<uint32_t*>(&t);
}

// ================= block reduce (256 thr, up to 5 scalars) =================
// scr must be float[48]: partials in [0,40), results in [40,45)
__device__ __forceinline__ void block_reduce(float* vals, int n, float* scr) {
    int tid = threadIdx.x, lane = tid & 31, wid = tid >> 5;
    for (int k = 0; k < n; k++) {
        float v = vals[k];
        #pragma unroll
        for (int o = 16; o; o >>= 1) v += __shfl_xor_sync(0xffffffffu, v, o);
        if (lane == 0) scr[k*8 + wid] = v;
    }
    __syncthreads();
    if (tid == 0) {
        for (int k = 0; k < n; k++) {
            float s = 0.f;
            #pragma unroll
            for (int w = 0; w < 8; w++) s += scr[k*8 + w];
            scr[40 + k] = s;
        }
    }
    __syncthreads();
    for (int k = 0; k < n; k++) vals[k] = scr[40 + k];
    __syncthreads();
}

// ================= LayerNorm (fp16 out) =================
__global__ void ln_half_kernel(const float* __restrict__ x, const float* __restrict__ w,
                               const float* __restrict__ b, __half* __restrict__ o) {
    __shared__ float scr[48];
    int row = blockIdx.x;
    const float* xr = x + (size_t)row * CC;
    int tid = threadIdx.x;
    float v2[2] = {0.f, 0.f};
    for (int i = tid; i < CC; i += 256) { float v = xr[i]; v2[0] += v; v2[1] += v*v; }
    block_reduce(v2, 2, scr);
    float mean = v2[0] * (1.0f/CC);
    float var  = v2[1] * (1.0f/CC) - mean*mean;
    float inv  = rsqrtf(var + 1e-5f);
    size_t base = (size_t)row * CC;
    for (int i = tid; i < CC; i += 256)
        o[base + i] = __float2half((xr[i] - mean) * inv * w[i] + b[i]);
}

// ================= fused LN1 + logmap -> fp16 pair =================
__global__ void logmap_fused(const float* __restrict__ x,
                             const float* __restrict__ w, const float* __restrict__ b,
                             __half* __restrict__ oh, __half* __restrict__ ol) {
    __shared__ float scr[48];
    __shared__ float un[CC], an[CC];
    int row = blockIdx.x;
    int t = row & (TT - 1);
    const float* xu = x + (size_t)row * CC;
    const float* xa = (t == 0) ? nullptr : xu - CC;
    int tid = threadIdx.x;

    // LN stats for row and row-1
    float v4[4] = {0.f, 0.f, 0.f, 0.f};
    for (int i = tid; i < CC; i += 256) {
        float vu = xu[i]; v4[0] += vu; v4[1] += vu*vu;
        if (xa) { float va = xa[i]; v4[2] += va; v4[3] += va*va; }
    }
    block_reduce(v4, 4, scr);
    float mu_u = v4[0] * (1.0f/CC);
    float inv_u = rsqrtf(v4[1] * (1.0f/CC) - mu_u*mu_u + 1e-5f);
    float mu_a = v4[2] * (1.0f/CC);
    float inv_a = rsqrtf(fmaxf(v4[3] * (1.0f/CC) - mu_a*mu_a, 0.f) + 1e-5f);

    // normalized rows + dot products
    float v3[3] = {0.f, 0.f, 0.f};   // an2, un2, ipau
    for (int i = tid; i < CC; i += 256) {
        float ui = (xu[i] - mu_u) * inv_u * w[i] + b[i];
        float ai = xa ? ((xa[i] - mu_a) * inv_a * w[i] + b[i]) : 0.f;
        un[i] = ui; an[i] = ai;
        v3[0] += ai*ai; v3[1] += ui*ui; v3[2] += ai*ui;
    }
    block_reduce(v3, 3, scr);
    float an2 = v3[0], un2 = v3[1], ipau = v3[2];

    float coefX = 1.f - 2.f*ipau + un2;
    float coefU = 1.f - an2;
    float rden  = 1.f / (1.f - 2.f*ipau + an2*un2);

    float mn2v[1] = {0.f};
    for (int i = tid; i < CC; i += 256) {
        float mi = (coefU * un[i] - coefX * an[i]) * rden;
        an[i] = mi;
        mn2v[0] += mi*mi;
    }
    block_reduce(mn2v, 1, scr);
    float mn = sqrtf(mn2v[0]);
    float cf = 1.f + an2;
    float arg = fminf(sqrtf(mn), 0.999f);
    float scale = cf * atanhf(arg) / mn;
    size_t base = (size_t)row * CC;
    for (int i = tid; i < CC; i += 256) {
        __half h, l; split2h(scale * an[i], h, l);
        oh[base + i] = h; ol[base + i] = l;
    }
}

// ================= fused LN1(row-1) + expmap: y fp32 -> fp16 =================
__global__ void expmap_fused(const float* __restrict__ x,
                             const float* __restrict__ w, const float* __restrict__ b,
                             const float* __restrict__ y, __half* __restrict__ o) {
    __shared__ float scr[48];
    __shared__ float rf[CC];
    int row = blockIdx.x;
    int t = row & (TT - 1);
    const float* xa = (t == 0) ? nullptr : x + (size_t)(row - 1) * CC;
    const float* v = y + (size_t)row * CC;
    int tid = threadIdx.x;

    float v2[2] = {0.f, 0.f};
    if (xa)
        for (int i = tid; i < CC; i += 256) { float va = xa[i]; v2[0] += va; v2[1] += va*va; }
    block_reduce(v2, 2, scr);
    float mu_a = v2[0] * (1.0f/CC);
    float inv_a = rsqrtf(fmaxf(v2[1] * (1.0f/CC) - mu_a*mu_a, 0.f) + 1e-5f);

    float v3[3] = {0.f, 0.f, 0.f};  // refn2, vn2, <ref,v>
    for (int i = tid; i < CC; i += 256) {
        float xi = xa ? ((xa[i] - mu_a) * inv_a * w[i] + b[i]) : 0.f;
        rf[i] = xi;
        float vi = v[i];
        v3[0] += xi*xi; v3[1] += vi*vi; v3[2] += xi*vi;
    }
    block_reduce(v3, 3, scr);
    float refn2 = v3[0], vn2 = v3[1], xv = v3[2];

    float lam = 2.f / (1.f + refn2);
    float vn  = sqrtf(vn2);
    float th  = tanhf(sqrtf(lam * vn2 * 0.5f));
    float ss  = th / vn;
    float secn2 = th * th;
    float ipxs  = ss * xv;
    float coefX = 1.f + 2.f*ipxs + secn2;
    float coefY = (1.f - refn2) * ss;
    float rden  = 1.f / (1.f + 2.f*ipxs + refn2*secn2);
    size_t base = (size_t)row * CC;
    for (int i = tid; i < CC; i += 256)
        o[base + i] = __float2half((coefX * rf[i] + coefY * v[i]) * rden);
}

// ================= weight transpose kernels =================
__global__ void wsplit_h_kernel(const float* __restrict__ W,
                                __half* __restrict__ Wh, __half* __restrict__ Wl,
                                int K, int N) {
    __shared__ float t[32][33];
    int n0 = blockIdx.x * 32, k0 = blockIdx.y * 32;
    int tx = threadIdx.x, ty = threadIdx.y;
    #pragma unroll
    for (int j = 0; j < 32; j += 8)
        t[ty + j][tx] = W[(size_t)(k0 + ty + j) * N + n0 + tx];
    __syncthreads();
    #pragma unroll
    for (int j = 0; j < 32; j += 8) {
        float v = t[tx][ty + j];
        __half h, l; split2h(v, h, l);
        size_t o = (size_t)(n0 + ty + j) * K + k0 + tx;
        Wh[o] = h; Wl[o] = l;
    }
}

__global__ void wtrans_h_kernel(const float* __restrict__ W, __half* __restrict__ Wt,
                                int K, int N) {
    __shared__ float t[32][33];
    int n0 = blockIdx.x * 32, k0 = blockIdx.y * 32;
    int tx = threadIdx.x, ty = threadIdx.y;
    #pragma unroll
    for (int j = 0; j < 32; j += 8)
        t[ty + j][tx] = W[(size_t)(k0 + ty + j) * N + n0 + tx];
    __syncthreads();
    #pragma unroll
    for (int j = 0; j < 32; j += 8)
        Wt[(size_t)(n0 + ty + j) * K + k0 + tx] = __float2half(t[tx][ty + j]);
}

// ================= shared tile loader =================
#define TILEB 16384
__device__ __forceinline__ void load_tile(uint32_t sdst, const void* gv,
                                          int row0, int Kd, int k0, int tid) {
    const __half* base = (const __half*)gv + (size_t)row0 * Kd + k0;
    #pragma unroll
    for (int i = 0; i < 4; i++) {
        int idx = tid * 4 + i;
        int r = idx >> 3, gc = idx & 7;
        uint32_t so = sdst + SWZ((uint32_t)(r * 128 + gc * 16));
        cp16(so, base + (size_t)r * Kd + gc * 8);
    }
}

// ================= QKV GEMM: fp16, 3 passes for Q/K cols, 1 pass for V cols =================
#define QSTAGEB (4*TILEB)
#define QGSMEM (3*QSTAGEB)

__global__ void __launch_bounds__(256, 1) gemm_qkv(
    const __half* __restrict__ Ah, const __half* __restrict__ Al,
    const __half* __restrict__ Bh, const __half* __restrict__ Bl,
    const float* __restrict__ bias,
    __half* __restrict__ Cqh, __half* __restrict__ Cql,
    __half* __restrict__ Ckh, __half* __restrict__ Ckl,
    __half* __restrict__ Cv)
{
    const int Kd = CC;
    extern __shared__ __align__(1024) char smem[];
    uint32_t sb = smem_u32(smem);
    int tid = threadIdx.x, wid = tid >> 5, lane = tid & 31;
    int wm = wid >> 2, wn = wid & 3;
    int bm = blockIdx.y * 128, bn = blockIdx.x * 128;
    const bool full = (bn < 2*CC);     // Q/K tiles: 3 passes; V tiles: 1 pass

    float acc[4][4][4];
    #pragma unroll
    for (int mt = 0; mt < 4; mt++)
        #pragma unroll
        for (int nt = 0; nt < 4; nt++)
            #pragma unroll
            for (int r = 0; r < 4; r++) acc[mt][nt][r] = 0.f;

    const int nch = Kd >> 6;

    #pragma unroll
    for (int s = 0; s < 3; s++) {
        uint32_t st = sb + s * QSTAGEB;
        int k0 = s * 64;
        load_tile(st,           Ah, bm, Kd, k0, tid);
        load_tile(st + 2*TILEB, Bh, bn, Kd, k0, tid);
        if (full) {
            load_tile(st +   TILEB, Al, bm, Kd, k0, tid);
            load_tile(st + 3*TILEB, Bl, bn, Kd, k0, tid);
        }
        CP_COMMIT();
    }

    int grp = lane >> 3, rw = lane & 7;
    int a_row = (grp & 1) * 8 + rw;
    int a_kb  = (grp >> 1) * 16;
    int b_row = (grp >> 1) * 8 + rw;
    int b_kb  = (grp & 1) * 16;

    for (int c = 0; c < nch; c++) {
        int rem = nch - 1 - c;
        if (rem >= 2) cpwait<2>(); else if (rem == 1) cpwait<1>(); else cpwait<0>();
        __syncthreads();
        uint32_t st = sb + (c % 3) * QSTAGEB;
        uint32_t Ahs = st, Als = st + TILEB, Bhs = st + 2*TILEB, Bls = st + 3*TILEB;

        #pragma unroll
        for (int kk = 0; kk < 4; kk++) {
            uint32_t ah[4][4], al[4][4], bh[4][2], bl[4][2];
            #pragma unroll
            for (int mt = 0; mt < 4; mt++) {
                uint32_t off = SWZ((uint32_t)((wm*64 + mt*16 + a_row) * 128 + kk*32 + a_kb));
                ldsm4(ah[mt][0], ah[mt][1], ah[mt][2], ah[mt][3], Ahs + off);
                if (full) ldsm4(al[mt][0], al[mt][1], al[mt][2], al[mt][3], Als + off);
            }
            #pragma unroll
            for (int p = 0; p < 2; p++) {
                uint32_t off = SWZ((uint32_t)((wn*32 + p*16 + b_row) * 128 + kk*32 + b_kb));
                ldsm4(bh[2*p][0], bh[2*p][1], bh[2*p+1][0], bh[2*p+1][1], Bhs + off);
                if (full) ldsm4(bl[2*p][0], bl[2*p][1], bl[2*p+1][0], bl[2*p+1][1], Bls + off);
            }
            #pragma unroll
            for (int mt = 0; mt < 4; mt++)
                #pragma unroll
                for (int nt = 0; nt < 4; nt++) {
                    mma_fp(acc[mt][nt], ah[mt], bh[nt]);
                    if (full) {
                        mma_fp(acc[mt][nt], ah[mt], bl[nt]);
                        mma_fp(acc[mt][nt], al[mt], bh[nt]);
                    }
                }
        }
        __syncthreads();
        int cn = c + 3;
        if (cn < nch) {
            uint32_t sd = sb + (cn % 3) * QSTAGEB;
            int k0 = cn * 64;
            load_tile(sd,           Ah, bm, Kd, k0, tid);
            load_tile(sd + 2*TILEB, Bh, bn, Kd, k0, tid);
            if (full) {
                load_tile(sd +   TILEB, Al, bm, Kd, k0, tid);
                load_tile(sd + 3*TILEB, Bl, bn, Kd, k0, tid);
            }
            CP_COMMIT();
        }
    }

    int r0 = lane >> 2, c0 = (lane & 3) * 2;
    #pragma unroll
    for (int mt = 0; mt < 4; mt++) {
        #pragma unroll
        for (int nt = 0; nt < 4; nt++) {
            int col = bn + wn*32 + nt*8 + c0;
            float b0 = bias[col], b1 = bias[col + 1];
            int part = col >> 10;
            int head = (col >> 6) & 15;
            int d    = col & 63;
            #pragma unroll
            for (int half = 0; half < 2; half++) {
                int row = bm + wm*64 + mt*16 + r0 + half*8;
                float v0 = acc[mt][nt][half*2]     + b0;
                float v1 = acc[mt][nt][half*2 + 1] + b1;
                size_t off = ((((size_t)(row >> 11)) * 16 + head) * TT + (row & 2047)) * 64 + d;
                if (part == 2) {
                    *reinterpret_cast<__half2*>(Cv + off) =
                        __half2(__float2half(v0), __float2half(v1));
                } else {
                    if (part == 0) { v0 *= QSCALE; v1 *= QSCALE; }
                    __half h0, l0, h1, l1;
                    split2h(v0, h0, l0); split2h(v1, h1, l1);
                    __half* Dh = (part == 0) ? Cqh : Ckh;
                    __half* Dl = (part == 0) ? Cql : Ckl;
                    *reinterpret_cast<__half2*>(Dh + off) = __half2(h0, h1);
                    *reinterpret_cast<__half2*>(Dl + off) = __half2(l0, l1);
                }
            }
        }
    }
}

// ================= fp16 x1 GEMM =================
// EPI 1: fp32 + residual      EPI 2: gelu -> fp16
#define F1STAGE (2*TILEB)
#define F1SMEM (2*F1STAGE)

template<int EPI>
__global__ void __launch_bounds__(256, 2) gemm_fp16(
    const __half* __restrict__ A, const __half* __restrict__ B,
    const float* __restrict__ bias, const float* __restrict__ res,
    float* __restrict__ Cf, __half* __restrict__ Co,
    int Nd, int Kd)
{
    extern __shared__ __align__(1024) char smem[];
    uint32_t sb = smem_u32(smem);
    int tid = threadIdx.x, wid = tid >> 5, lane = tid & 31;
    int wm = wid >> 2, wn = wid & 3;
    int bm = blockIdx.y * 128, bn = blockIdx.x * 128;

    float acc[4][4][4];
    #pragma unroll
    for (int mt = 0; mt < 4; mt++)
        #pragma unroll
        for (int nt = 0; nt < 4; nt++)
            #pragma unroll
            for (int r = 0; r < 4; r++) acc[mt][nt][r] = 0.f;

    int nch = Kd >> 6;

    #pragma unroll
    for (int s = 0; s < 2; s++) {
        uint32_t st = sb + s * F1STAGE;
        int k0 = s * 64;
        load_tile(st,         A, bm, Kd, k0, tid);
        load_tile(st + TILEB, B, bn, Kd, k0, tid);
        CP_COMMIT();
    }

    int grp = lane >> 3, rw = lane & 7;
    int a_row = (grp & 1) * 8 + rw;
    int a_kb  = (grp >> 1) * 16;
    int b_row = (grp >> 1) * 8 + rw;
    int b_kb  = (grp & 1) * 16;

    for (int c = 0; c < nch; c++) {
        if (c + 1 < nch) cpwait<1>(); else cpwait<0>();
        __syncthreads();
        uint32_t st = sb + (c & 1) * F1STAGE;
        uint32_t As = st, Bs = st + TILEB;

        #pragma unroll
        for (int kk = 0; kk < 4; kk++) {
            uint32_t af[4][4], bf[4][2];
            #pragma unroll
            for (int mt = 0; mt < 4; mt++) {
                uint32_t off = SWZ((uint32_t)((wm*64 + mt*16 + a_row) * 128 + kk*32 + a_kb));
                ldsm4(af[mt][0], af[mt][1], af[mt][2], af[mt][3], As + off);
            }
            #pragma unroll
            for (int p = 0; p < 2; p++) {
                uint32_t off = SWZ((uint32_t)((wn*32 + p*16 + b_row) * 128 + kk*32 + b_kb));
                ldsm4(bf[2*p][0], bf[2*p][1], bf[2*p+1][0], bf[2*p+1][1], Bs + off);
            }
            #pragma unroll
            for (int mt = 0; mt < 4; mt++)
                #pragma unroll
                for (int nt = 0; nt < 4; nt++)
                    mma_fp(acc[mt][nt], af[mt], bf[nt]);
        }
        __syncthreads();
        int cn = c + 2;
        if (cn < nch) {
            int k0 = cn * 64;
            load_tile(st,         A, bm, Kd, k0, tid);
            load_tile(st + TILEB, B, bn, Kd, k0, tid);
            CP_COMMIT();
        }
    }

    int r0 = lane >> 2, c0 = (lane & 3) * 2;
    #pragma unroll
    for (int mt = 0; mt < 4; mt++) {
        #pragma unroll
        for (int nt = 0; nt < 4; nt++) {
            int col = bn + wn*32 + nt*8 + c0;
            float b0 = bias[col], b1 = bias[col + 1];
            #pragma unroll
            for (int half = 0; half < 2; half++) {
                int row = bm + wm*64 + mt*16 + r0 + half*8;
                float v0 = acc[mt][nt][half*2]     + b0;
                float v1 = acc[mt][nt][half*2 + 1] + b1;
                size_t off = (size_t)row * Nd + col;
                if (EPI == 2) {
                    v0 = v0 * normcdff(v0);
                    v1 = v1 * normcdff(v1);
                    *reinterpret_cast<__half2*>(Co + off) =
                        __half2(__float2half(v0), __float2half(v1));
                } else {
                    v0 += res[off]; v1 += res[off + 1];
                    *reinterpret_cast<float2*>(Cf + off) = make_float2(v0, v1);
                }
            }
        }
    }
}

// ================= flash attention: QK fp16x3, PV fp16x1 =================
#define ATSTG 24576
#define AT_SMEM (32768 + 2*ATSTG)   // 81920

__device__ __forceinline__ void load_kv(uint32_t st,
        const __half* khp, const __half* klp,
        const __half* vp, int kt, int tid) {
    int k0 = kt * 64;
    #pragma unroll
    for (int i = 0; i < 2; i++) {
        int idx = tid * 2 + i;
        int r = idx >> 3, gc = idx & 7;
        uint32_t off = SWZ((uint32_t)(r * 128 + gc * 16));
        size_t g = (size_t)(k0 + r) * 64 + gc * 8;
        cp16(st + off,         khp + g);
        cp16(st + 8192 + off,  klp + g);
        cp16(st + 16384 + off, vp + g);
    }
}

__global__ void __launch_bounds__(256, 1) attn_hmma(
    const __half* __restrict__ Qh, const __half* __restrict__ Ql,
    const __half* __restrict__ Kh, const __half* __restrict__ Kl,
    const __half* __restrict__ V,
    float* __restrict__ y)
{
    extern __shared__ __align__(1024) char smem[];
    uint32_t sb = smem_u32(smem);
    int tid = threadIdx.x, wid = tid >> 5, lane = tid & 31;
    int bhx = blockIdx.y, b = bhx >> 4, h = bhx & 15;
    // reversed q order: heavy (late-q) blocks launch first for causal load balance
    int qblk = gridDim.x - 1 - blockIdx.x;
    int q0 = qblk * 128;
    size_t hb = (size_t)bhx * TT * DH;
    const __half *qhp = Qh + hb, *qlp = Ql + hb;
    const __half *khp = Kh + hb, *klp = Kl + hb;
    const __half *vp = V + hb;

    uint32_t sQh = sb, sQl = sb + 16384;
    uint32_t stg0 = sb + 32768, stg1 = sb + 32768 + ATSTG;

    int ntiles = 2 * (qblk + 1);

    load_tile(sQh, qhp, q0, 64, 0, tid);
    load_tile(sQl, qlp, q0, 64, 0, tid);
    load_kv(stg0, khp, klp, vp, 0, tid);
    CP_COMMIT();
    if (ntiles > 1) { load_kv(stg1, khp, klp, vp, 1, tid); CP_COMMIT(); }
    if (ntiles > 1) cpwait<1>(); else cpwait<0>();
    __syncthreads();

    int grp = lane >> 3, rw = lane & 7;
    int a_row = (grp & 1) * 8 + rw, a_kb = (grp >> 1) * 16;
    int b_row = (grp >> 1) * 8 + rw, b_kb = (grp & 1) * 16;
    int v_row = (grp & 1) * 8 + rw,  v_db = (grp >> 1) * 16;

    uint32_t qfh[4][4], qfl[4][4];
    #pragma unroll
    for (int kk = 0; kk < 4; kk++) {
        uint32_t off = SWZ((uint32_t)((wid*16 + a_row) * 128 + kk*32 + a_kb));
        ldsm4(qfh[kk][0], qfh[kk][1], qfh[kk][2], qfh[kk][3], sQh + off);
        ldsm4(qfl[kk][0], qfl[kk][1], qfl[kk][2], qfl[kk][3], sQl + off);
    }

    float o[8][4];
    #pragma unroll
    for (int nt = 0; nt < 8; nt++)
        #pragma unroll
        for (int r = 0; r < 4; r++) o[nt][r] = 0.f;
    float m0 = -1e30f, m1 = -1e30f, l0 = 0.f, l1 = 0.f;

    int qr0 = q0 + wid*16 + (lane >> 2);
    int kc0 = (lane & 3) * 2;

    for (int kt = 0; kt < ntiles; kt++) {
        if (kt > 0) {
            if (kt + 1 < ntiles) cpwait<1>(); else cpwait<0>();
            __syncthreads();
        }
        uint32_t st = (kt & 1) ? stg1 : stg0;
        int k0 = kt * 64;
        if (k0 <= q0 + wid*16 + 15) {
            uint32_t sKh = st, sKl = st + 8192, sV = st + 16384;
            float s[8][4];
            #pragma unroll
            for (int nt = 0; nt < 8; nt++)
                #pragma unroll
                for (int r = 0; r < 4; r++) s[nt][r] = 0.f;

            #pragma unroll
            for (int kk = 0; kk < 4; kk++) {
                uint32_t bhf[8][2], blf[8][2];
                #pragma unroll
                for (int p = 0; p < 4; p++) {
                    uint32_t off = SWZ((uint32_t)((p*16 + b_row) * 128 + kk*32 + b_kb));
                    ldsm4(bhf[2*p][0], bhf[2*p][1], bhf[2*p+1][0], bhf[2*p+1][1], sKh + off);
                    ldsm4(blf[2*p][0], blf[2*p][1], blf[2*p+1][0], blf[2*p+1][1], sKl + off);
                }
                #pragma unroll
                for (int nt = 0; nt < 8; nt++) {
                    mma_fp(s[nt], qfh[kk], bhf[nt]);
                    mma_fp(s[nt], qfh[kk], blf[nt]);
                    mma_fp(s[nt], qfl[kk], bhf[nt]);
                }
            }

            if (k0 + 63 > qr0) {
                #pragma unroll
                for (int nt = 0; nt < 8; nt++) {
                    int kg = k0 + nt*8 + kc0;
                    if (kg     > qr0)     s[nt][0] = -1e30f;
                    if (kg + 1 > qr0)     s[nt][1] = -1e30f;
                    if (kg     > qr0 + 8) s[nt][2] = -1e30f;
                    if (kg + 1 > qr0 + 8) s[nt][3] = -1e30f;
                }
            }

            float t0 = -1e30f, t1 = -1e30f;
            #pragma unroll
            for (int nt = 0; nt < 8; nt++) {
                t0 = fmaxf(t0, fmaxf(s[nt][0], s[nt][1]));
                t1 = fmaxf(t1, fmaxf(s[nt][2], s[nt][3]));
            }
            t0 = fmaxf(t0, __shfl_xor_sync(0xffffffffu, t0, 1));
            t0 = fmaxf(t0, __shfl_xor_sync(0xffffffffu, t0, 2));
            t1 = fmaxf(t1, __shfl_xor_sync(0xffffffffu, t1, 1));
            t1 = fmaxf(t1, __shfl_xor_sync(0xffffffffu, t1, 2));
            float mn0 = fmaxf(m0, t0), mn1 = fmaxf(m1, t1);
            float al0 = ex2f(m0 - mn0), al1 = ex2f(m1 - mn1);
            m0 = mn0; m1 = mn1;

            float ps0 = 0.f, ps1 = 0.f;
            uint32_t pa[4][4];
            #pragma unroll
            for (int nt = 0; nt < 8; nt++) {
                float p0 = ex2f(s[nt][0] - m0), p1 = ex2f(s[nt][1] - m0);
                float p2 = ex2f(s[nt][2] - m1), p3 = ex2f(s[nt][3] - m1);
                ps0 += p0 + p1; ps1 += p2 + p3;
                int jj = nt >> 1, rb = (nt & 1) * 2;
                pa[jj][rb]   = pack2h(__float2half(p0), __float2half(p1));
                pa[jj][rb+1] = pack2h(__float2half(p2), __float2half(p3));
            }
            ps0 += __shfl_xor_sync(0xffffffffu, ps0, 1);
            ps0 += __shfl_xor_sync(0xffffffffu, ps0, 2);
            ps1 += __shfl_xor_sync(0xffffffffu, ps1, 1);
            ps1 += __shfl_xor_sync(0xffffffffu, ps1, 2);
            l0 = al0 * l0 + ps0;
            l1 = al1 * l1 + ps1;
            #pragma unroll
            for (int nt = 0; nt < 8; nt++) {
                o[nt][0] *= al0; o[nt][1] *= al0;
                o[nt][2] *= al1; o[nt][3] *= al1;
            }

            #pragma unroll
            for (int j = 0; j < 4; j++) {
                uint32_t vf[8][2];
                #pragma unroll
                for (int p = 0; p < 4; p++) {
                    uint32_t off = SWZ((uint32_t)((j*16 + v_row) * 128 + p*32 + v_db));
                    ldsm4t(vf[2*p][0], vf[2*p][1], vf[2*p+1][0], vf[2*p+1][1], sV + off);
                }
                #pragma unroll
                for (int nt = 0; nt < 8; nt++)
                    mma_fp(o[nt], pa[j], vf[nt]);
            }
        }
        __syncthreads();
        if (kt + 2 < ntiles) {
            load_kv((kt & 1) ? stg1 : stg0, khp, klp, vp, kt + 2, tid);
            CP_COMMIT();
        }
    }

    float rl0 = 1.f / l0, rl1 = 1.f / l1;
    size_t base0 = ((size_t)(b*TT + qr0) * CC) + h*64 + kc0;
    size_t base1 = base0 + (size_t)8 * CC;
    #pragma unroll
    for (int nt = 0; nt < 8; nt++) {
        *reinterpret_cast<float2*>(y + base0 + nt*8) = make_float2(o[nt][0]*rl0, o[nt][1]*rl0);
        *reinterpret_cast<float2*>(y + base1 + nt*8) = make_float2(o[nt][2]*rl1, o[nt][3]*rl1);
    }
}

// ================= launch =================
extern "C" void kernel_launch(void* const* d_in, const int* in_sizes, int n_in,
                              void* d_out, int out_size) {
    const float* x       = (const float*)d_in[0];
    const float* ln1_w   = (const float*)d_in[1];
    const float* ln1_b   = (const float*)d_in[2];
    const float* W_attn  = (const float*)d_in[3];
    const float* b_attn  = (const float*)d_in[4];
    const float* W_aproj = (const float*)d_in[5];
    const float* b_aproj = (const float*)d_in[6];
    const float* ln2_w   = (const float*)d_in[7];
    const float* ln2_b   = (const float*)d_in[8];
    const float* W_fc    = (const float*)d_in[9];
    const float* b_fc    = (const float*)d_in[10];
    const float* W_mproj = (const float*)d_in[11];
    const float* b_mproj = (const float*)d_in[12];
    float* out = (float*)d_out;

    float *y, *x1;
    __half *xth, *xtl, *qh, *ql, *kh, *kl, *v, *yh, *hh, *fch;
    __half *wah, *wal, *wap, *wfc, *wmp;
    cudaGetSymbolAddress((void**)&y,   g_y);
    cudaGetSymbolAddress((void**)&x1,  g_x1);
    cudaGetSymbolAddress((void**)&xth, g_xt_h); cudaGetSymbolAddress((void**)&xtl, g_xt_l);
    cudaGetSymbolAddress((void**)&yh,  g_yh);
    cudaGetSymbolAddress((void**)&hh,  g_hh);
    cudaGetSymbolAddress((void**)&fch, g_fch);
    cudaGetSymbolAddress((void**)&qh, g_qh); cudaGetSymbolAddress((void**)&ql, g_ql);
    cudaGetSymbolAddress((void**)&kh, g_kh); cudaGetSymbolAddress((void**)&kl, g_kl);
    cudaGetSymbolAddress((void**)&v,  g_v);
    cudaGetSymbolAddress((void**)&wah, g_wattn_h); cudaGetSymbolAddress((void**)&wal, g_wattn_l);
    cudaGetSymbolAddress((void**)&wap, g_waproj);
    cudaGetSymbolAddress((void**)&wfc, g_wfc);
    cudaGetSymbolAddress((void**)&wmp, g_wmproj);

    cudaFuncSetAttribute(attn_hmma, cudaFuncAttributeMaxDynamicSharedMemorySize, AT_SMEM);
    cudaFuncSetAttribute(gemm_qkv, cudaFuncAttributeMaxDynamicSharedMemorySize, QGSMEM);
    cudaFuncSetAttribute(gemm_fp16<1>, cudaFuncAttributeMaxDynamicSharedMemorySize, F1SMEM);
    cudaFuncSetAttribute(gemm_fp16<2>, cudaFuncAttributeMaxDynamicSharedMemorySize, F1SMEM);

    dim3 tb(32, 8);
    wsplit_h_kernel<<<dim3(3*CC/32, CC/32), tb>>>(W_attn,  wah, wal, CC, 3*CC);
    wtrans_h_kernel<<<dim3(CC/32,   CC/32), tb>>>(W_aproj, wap, CC,   CC);
    wtrans_h_kernel<<<dim3(4*CC/32, CC/32), tb>>>(W_fc,    wfc, CC,   4*CC);
    wtrans_h_kernel<<<dim3(CC/32, 4*CC/32), tb>>>(W_mproj, wmp, 4*CC, CC);

    // 1. fused LN1 + logmap -> fp16 pair
    logmap_fused<<<NROWS, 256>>>(x, ln1_w, ln1_b, xth, xtl);
    // 2. QKV GEMM (fp16; QK x3, V x1) -> Q/K pairs + V
    gemm_qkv<<<dim3(3*CC/128, NROWS/128), 256, QGSMEM>>>(
        xth, xtl, wah, wal, b_attn, qh, ql, kh, kl, v);
    // 3. attention
    attn_hmma<<<dim3(TT/128, BB*HH), 256, AT_SMEM>>>(qh, ql, kh, kl, v, y);
    // 4. fused LN1(row-1) + expmap -> fp16
    expmap_fused<<<NROWS, 256>>>(x, ln1_w, ln1_b, y, yh);
    // 5. aproj + residual -> x1 fp32
    gemm_fp16<1><<<dim3(CC/128, NROWS/128), 256, F1SMEM>>>(
        yh, wap, b_aproj, x, x1, nullptr, CC, CC);
    // 6. LN2 -> fp16
    ln_half_kernel<<<NROWS, 256>>>(x1, ln2_w, ln2_b, hh);
    // 7. FC + GELU -> fp16
    gemm_fp16<2><<<dim3(4*CC/128, NROWS/128), 256, F1SMEM>>>(
        hh, wfc, b_fc, nullptr, nullptr, fch, 4*CC, CC);
    // 8. mproj + residual -> out
    gemm_fp16<1><<<dim3(CC/128, NROWS/128), 256, F1SMEM>>>(
        fch, wmp, b_mproj, x1, out, nullptr, CC, 4*CC);
}